// round 7
// baseline (speedup 1.0000x reference)
#include <cuda_runtime.h>
#include <cuda_bf16.h>
#include <cuda_fp16.h>
#include <cstdint>
#include <cstddef>

// ---------------------------------------------------------------------------
// MultiHeadAttention: x@W_attn+b -> causal MHA -> @W_proj+b
// B=2, T=2048, C=1024, H=16, D=64.
// Round 7: GEMM1 deduplicated bf16 3-term split (hi/lo packed per smem row);
// attention split-bf16 QK^T + fp16 PV; GEMM2 fp16 2-term split.
// ---------------------------------------------------------------------------

#define BB 2
#define TT 2048
#define CC 1024
#define NH 16
#define HD 64
#define MTOT (BB * TT)  // 4096
#define K2 (2 * CC)     // 2048 (GEMM2 split K)

// ------------------------------ scratch ------------------------------------
__device__ __nv_bfloat16 g_ahi[MTOT * CC];        // x hi/lo split
__device__ __nv_bfloat16 g_alo[MTOT * CC];
__device__ __nv_bfloat16 g_wahi[3 * CC * CC];     // W_attn^T hi/lo [3C][C]
__device__ __nv_bfloat16 g_walo[3 * CC * CC];
__device__ __half        g_wp2[CC * K2];          // W_proj^T [C][2K]=[hi|lo]
__device__ __half        g_y2[MTOT * K2];         // y fp16 [M][2K]=[y|y]
__device__ __nv_bfloat16 g_qhi[BB * NH * TT * HD];
__device__ __nv_bfloat16 g_qlo[BB * NH * TT * HD];
__device__ __nv_bfloat16 g_khi[BB * NH * TT * HD];
__device__ __nv_bfloat16 g_klo[BB * NH * TT * HD];
__device__ __half        g_v[BB * NH * TT * HD];

// ------------------------------ helpers ------------------------------------
__device__ __forceinline__ uint32_t smem_u32(const void* p) {
    uint32_t a;
    asm("{ .reg .u64 t; cvta.to.shared.u64 t, %1; cvt.u32.u64 %0, t; }"
        : "=r"(a) : "l"(p));
    return a;
}
__device__ __forceinline__ uint32_t swz(uint32_t x) {  // SW128 (128B rows)
    return x ^ ((x >> 3) & 0x70);
}
__device__ __forceinline__ void cp16(uint32_t dst, const void* src) {
    asm volatile("cp.async.cg.shared.global [%0], [%1], 16;"
                 :: "r"(dst), "l"(src));
}
__device__ __forceinline__ void cp_commit() {
    asm volatile("cp.async.commit_group;");
}
template <int N>
__device__ __forceinline__ void cp_wait() {
    asm volatile("cp.async.wait_group %0;" :: "n"(N));
}
__device__ __forceinline__ void ldsm4(uint32_t& r0, uint32_t& r1, uint32_t& r2,
                                      uint32_t& r3, uint32_t addr) {
    asm volatile("ldmatrix.sync.aligned.m8n8.x4.shared.b16 {%0,%1,%2,%3}, [%4];"
                 : "=r"(r0), "=r"(r1), "=r"(r2), "=r"(r3) : "r"(addr));
}
__device__ __forceinline__ void ldsm4t(uint32_t& r0, uint32_t& r1, uint32_t& r2,
                                       uint32_t& r3, uint32_t addr) {
    asm volatile(
        "ldmatrix.sync.aligned.m8n8.x4.trans.shared.b16 {%0,%1,%2,%3}, [%4];"
        : "=r"(r0), "=r"(r1), "=r"(r2), "=r"(r3) : "r"(addr));
}
__device__ __forceinline__ void mma_bf16(float* c, const uint32_t* a,
                                         const uint32_t* b) {
    asm volatile(
        "mma.sync.aligned.m16n8k16.row.col.f32.bf16.bf16.f32 "
        "{%0,%1,%2,%3}, {%4,%5,%6,%7}, {%8,%9}, {%0,%1,%2,%3};"
        : "+f"(c[0]), "+f"(c[1]), "+f"(c[2]), "+f"(c[3])
        : "r"(a[0]), "r"(a[1]), "r"(a[2]), "r"(a[3]), "r"(b[0]), "r"(b[1]));
}
__device__ __forceinline__ void mma_f16(float* c, const uint32_t* a,
                                        const uint32_t* b) {
    asm volatile(
        "mma.sync.aligned.m16n8k16.row.col.f32.f16.f16.f32 "
        "{%0,%1,%2,%3}, {%4,%5,%6,%7}, {%8,%9}, {%0,%1,%2,%3};"
        : "+f"(c[0]), "+f"(c[1]), "+f"(c[2]), "+f"(c[3])
        : "r"(a[0]), "r"(a[1]), "r"(a[2]), "r"(a[3]), "r"(b[0]), "r"(b[1]));
}
__device__ __forceinline__ uint32_t packh2(float a, float b) {
    __half2 h = __floats2half2_rn(a, b);
    return *reinterpret_cast<uint32_t*>(&h);
}

// ---------------------------------------------------------------------------
// convert_split2: X fp32 -> Hi, Lo bf16 (elementwise, same layout)
// ---------------------------------------------------------------------------
__global__ __launch_bounds__(256) void convert_split2_kernel(
    const float* __restrict__ X, __nv_bfloat16* __restrict__ Hi,
    __nv_bfloat16* __restrict__ Lo, int n4)
{
    int i = blockIdx.x * blockDim.x + threadIdx.x;
    if (i >= n4) return;
    float4 v = ((const float4*)X)[i];
    float vv[4] = {v.x, v.y, v.z, v.w};
    __nv_bfloat16 h[4], l[4];
#pragma unroll
    for (int j = 0; j < 4; ++j) {
        h[j] = __float2bfloat16(vv[j]);
        l[j] = __float2bfloat16(vv[j] - __bfloat162float(h[j]));
    }
    ((__nv_bfloat162*)Hi)[i * 2 + 0] = __nv_bfloat162(h[0], h[1]);
    ((__nv_bfloat162*)Hi)[i * 2 + 1] = __nv_bfloat162(h[2], h[3]);
    ((__nv_bfloat162*)Lo)[i * 2 + 0] = __nv_bfloat162(l[0], l[1]);
    ((__nv_bfloat162*)Lo)[i * 2 + 1] = __nv_bfloat162(l[2], l[3]);
}

// ---------------------------------------------------------------------------
// transpose_split2_pair: W [K][N] fp32 -> Hi, Lo [N][K] bf16
// ---------------------------------------------------------------------------
__global__ __launch_bounds__(256) void transpose_split2_pair_kernel(
    const float* __restrict__ W, __nv_bfloat16* __restrict__ Hi,
    __nv_bfloat16* __restrict__ Lo, int K, int N)
{
    __shared__ float t[32][33];
    const int n0 = blockIdx.x * 32, k0 = blockIdx.y * 32;
    const int tx = threadIdx.x, ty = threadIdx.y;
#pragma unroll
    for (int i = 0; i < 32; i += 8)
        t[ty + i][tx] = W[(size_t)(k0 + ty + i) * N + n0 + tx];
    __syncthreads();
#pragma unroll
    for (int i = 0; i < 32; i += 8) {
        const int n = n0 + ty + i, k = k0 + tx;
        const float v = t[tx][ty + i];
        const __nv_bfloat16 h = __float2bfloat16(v);
        Hi[(size_t)n * K + k] = h;
        Lo[(size_t)n * K + k] = __float2bfloat16(v - __bfloat162float(h));
    }
}

// ---------------------------------------------------------------------------
// transpose_split2_f16: W [K][N] fp32 -> B2 [N][2K] fp16 = [hi | lo]
// ---------------------------------------------------------------------------
__global__ __launch_bounds__(256) void transpose_split2_f16_kernel(
    const float* __restrict__ W, __half* __restrict__ B2, int K, int N)
{
    __shared__ float t[32][33];
    const int n0 = blockIdx.x * 32, k0 = blockIdx.y * 32;
    const int tx = threadIdx.x, ty = threadIdx.y;
#pragma unroll
    for (int i = 0; i < 32; i += 8)
        t[ty + i][tx] = W[(size_t)(k0 + ty + i) * N + n0 + tx];
    __syncthreads();
#pragma unroll
    for (int i = 0; i < 32; i += 8) {
        const int n = n0 + ty + i, k = k0 + tx;
        const float v = t[tx][ty + i];
        const __half h = __float2half_rn(v);
        __half* row = B2 + (size_t)n * (2 * K);
        row[k] = h;
        row[K + k] = __float2half_rn(v - __half2float(h));
    }
}

// ---------------------------------------------------------------------------
// GEMM1 (QKV): C = (Ahi+Alo)(Bhi+Blo)^T + bias, 3-term bf16 split, K=1024.
// CTA 128x128, BK=32, 3 stages (32KB each), 2 CTA/SM, 8 warps (2x4).
// smem row (128B) = [hi 64B | lo 64B]; each ldsm'd fragment feeds 3 terms.
// Epilogue: split Q/K bf16 + V fp16, head-major; Q pre-scaled by 0.125.
// ---------------------------------------------------------------------------
#define G1_TILEA 16384    // 128 rows x 128B (hi|lo)
#define G1_STAGE 32768    // A + B
#define G1_NSTAGE 3
#define G1_NCH (CC / 32)  // 32

__global__ __launch_bounds__(256, 2) void gemm1_kernel(
    const __nv_bfloat16* __restrict__ Ahi, const __nv_bfloat16* __restrict__ Alo,
    const __nv_bfloat16* __restrict__ Bhi, const __nv_bfloat16* __restrict__ Blo,
    const float* __restrict__ bias,
    __nv_bfloat16* __restrict__ Qhi, __nv_bfloat16* __restrict__ Qlo,
    __nv_bfloat16* __restrict__ Khi, __nv_bfloat16* __restrict__ Klo,
    __half* __restrict__ Vh)
{
    extern __shared__ char dsm[];
    const uint32_t sbase = smem_u32(dsm);

    const int tid = threadIdx.x;
    const int lane = tid & 31;
    const int warp = tid >> 5;
    const int wm = warp >> 2;
    const int wn = warp & 3;
    const int n0 = blockIdx.x * 128;
    const int m0 = blockIdx.y * 128;

    // cp.async mapping: row = tid>>1, sub = tid&1 picks hi(0)/lo(1) plane.
    const int ldrow = tid >> 1;
    const int sub = tid & 1;
    const __nv_bfloat16* aSrc =
        (sub ? Alo : Ahi) + (size_t)(m0 + ldrow) * CC;
    const __nv_bfloat16* bSrc =
        (sub ? Blo : Bhi) + (size_t)(n0 + ldrow) * CC;
    uint32_t dstOff[4];
#pragma unroll
    for (int j = 0; j < 4; ++j)
        dstOff[j] = swz(ldrow * 128 + sub * 64 + j * 16);

#pragma unroll
    for (int c = 0; c < G1_NSTAGE - 1; ++c) {  // prologue: chunks 0,1
        const uint32_t sA = sbase + c * G1_STAGE;
        const uint32_t sB = sA + G1_TILEA;
#pragma unroll
        for (int j = 0; j < 4; ++j) {
            cp16(sA + dstOff[j], aSrc + c * 32 + j * 8);
            cp16(sB + dstOff[j], bSrc + c * 32 + j * 8);
        }
        cp_commit();
    }

    float acc[4][4][4];
#pragma unroll
    for (int i = 0; i < 4; ++i)
#pragma unroll
        for (int j = 0; j < 4; ++j)
#pragma unroll
            for (int r = 0; r < 4; ++r) acc[i][j][r] = 0.f;

    const int arow = wm * 64 + (lane & 15);
    const uint32_t acolbase = (lane >> 4) << 4;
    const int brow = wn * 32 + ((lane >> 4) << 3) + (lane & 7);
    const uint32_t bcolbase = ((lane >> 3) & 1) << 4;

    for (int c = 0; c < G1_NCH; ++c) {
        cp_wait<G1_NSTAGE - 2>();
        __syncthreads();  // also orders prev-iter reads before next writes

        if (c + G1_NSTAGE - 1 < G1_NCH) {
            const int cc = c + G1_NSTAGE - 1;
            const uint32_t sA = sbase + (cc % G1_NSTAGE) * G1_STAGE;
            const uint32_t sB = sA + G1_TILEA;
#pragma unroll
            for (int j = 0; j < 4; ++j) {
                cp16(sA + dstOff[j], aSrc + cc * 32 + j * 8);
                cp16(sB + dstOff[j], bSrc + cc * 32 + j * 8);
            }
        }
        cp_commit();

        const uint32_t sA = sbase + (c % G1_NSTAGE) * G1_STAGE;
        const uint32_t sB = sA + G1_TILEA;

#pragma unroll
        for (int kk = 0; kk < 2; ++kk) {
            uint32_t bh[2][4], bl[2][4], af[4][4];
#pragma unroll
            for (int fn2 = 0; fn2 < 2; ++fn2) {
                const uint32_t rb = (uint32_t)(brow + fn2 * 16) * 128;
                ldsm4(bh[fn2][0], bh[fn2][1], bh[fn2][2], bh[fn2][3],
                      sB + swz(rb + kk * 32 + bcolbase));
                ldsm4(bl[fn2][0], bl[fn2][1], bl[fn2][2], bl[fn2][3],
                      sB + swz(rb + 64 + kk * 32 + bcolbase));
            }
#pragma unroll
            for (int fm = 0; fm < 4; ++fm) {
                const uint32_t ra = (uint32_t)(arow + fm * 16) * 128;
                ldsm4(af[fm][0], af[fm][1], af[fm][2], af[fm][3],
                      sA + swz(ra + kk * 32 + acolbase));
            }
#pragma unroll
            for (int fm = 0; fm < 4; ++fm)
#pragma unroll
                for (int fn = 0; fn < 4; ++fn) {
                    mma_bf16(acc[fm][fn], af[fm], &bh[fn >> 1][(fn & 1) * 2]);
                    mma_bf16(acc[fm][fn], af[fm], &bl[fn >> 1][(fn & 1) * 2]);
                }
#pragma unroll
            for (int fm = 0; fm < 4; ++fm) {  // overwrite with Alo
                const uint32_t ra = (uint32_t)(arow + fm * 16) * 128;
                ldsm4(af[fm][0], af[fm][1], af[fm][2], af[fm][3],
                      sA + swz(ra + 64 + kk * 32 + acolbase));
            }
#pragma unroll
            for (int fm = 0; fm < 4; ++fm)
#pragma unroll
                for (int fn = 0; fn < 4; ++fn)
                    mma_bf16(acc[fm][fn], af[fm], &bh[fn >> 1][(fn & 1) * 2]);
        }
    }

    // ---- QKV epilogue: split Q/K bf16 + V fp16, head-major ----
#pragma unroll
    for (int fm = 0; fm < 4; ++fm) {
        const int r0 = m0 + wm * 64 + fm * 16 + (lane >> 2);
#pragma unroll
        for (int fn = 0; fn < 4; ++fn) {
            const int cidx = n0 + wn * 32 + fn * 8 + (lane & 3) * 2;
            const float b0 = bias[cidx], b1 = bias[cidx + 1];
            const int reg = cidx >> 10;
            const int idx = cidx & 1023;
            const int h = idx >> 6, d = idx & 63;
#pragma unroll
            for (int rr = 0; rr < 2; ++rr) {
                const int m = r0 + rr * 8;
                const int bb = m >> 11, t = m & 2047;
                float va = (rr ? acc[fm][fn][2] : acc[fm][fn][0]) + b0;
                float vb = (rr ? acc[fm][fn][3] : acc[fm][fn][1]) + b1;
                const size_t off = ((size_t)(bb * NH + h) * TT + t) * HD + d;
                if (reg == 0) {
                    va *= 0.125f; vb *= 0.125f;
                    __nv_bfloat16 ha = __float2bfloat16(va);
                    __nv_bfloat16 hb = __float2bfloat16(vb);
                    *(__nv_bfloat162*)&Qhi[off] = __nv_bfloat162(ha, hb);
                    *(__nv_bfloat162*)&Qlo[off] = __nv_bfloat162(
                        __float2bfloat16(va - __bfloat162float(ha)),
                        __float2bfloat16(vb - __bfloat162float(hb)));
                } else if (reg == 1) {
                    __nv_bfloat16 ha = __float2bfloat16(va);
                    __nv_bfloat16 hb = __float2bfloat16(vb);
                    *(__nv_bfloat162*)&Khi[off] = __nv_bfloat162(ha, hb);
                    *(__nv_bfloat162*)&Klo[off] = __nv_bfloat162(
                        __float2bfloat16(va - __bfloat162float(ha)),
                        __float2bfloat16(vb - __bfloat162float(hb)));
                } else {
                    *(__half2*)&Vh[off] = __floats2half2_rn(va, vb);
                }
            }
        }
    }
}

// ---------------------------------------------------------------------------
// GEMM2 (proj): fp16 2-term split, A=[y|y], B=[Whi|Wlo], K'=2048.
// CTA 128x128, BK=64, 3 stages, 2 CTA/SM.
// ---------------------------------------------------------------------------
#define BKB 128
#define TILE_A 16384
#define STAGE 32768
#define NSTAGE 3

__global__ __launch_bounds__(256, 2) void gemm2_kernel(
    const __half* __restrict__ A, const __half* __restrict__ B,
    const float* __restrict__ bias, float* __restrict__ Cout, int N, int Klen)
{
    extern __shared__ char dsm[];
    const uint32_t sbase = smem_u32(dsm);

    const int tid = threadIdx.x;
    const int lane = tid & 31;
    const int warp = tid >> 5;
    const int wm = warp >> 2;
    const int wn = warp & 3;
    const int n0 = blockIdx.x * 128;
    const int m0 = blockIdx.y * 128;

    const int ldrow = tid >> 1;
    const int cgrp = (tid & 1) * 4;
    const __half* aRow = A + (size_t)(m0 + ldrow) * Klen + cgrp * 8;
    const __half* bRow = B + (size_t)(n0 + ldrow) * Klen + cgrp * 8;
    uint32_t dstOff[4];
#pragma unroll
    for (int j = 0; j < 4; ++j)
        dstOff[j] = swz(ldrow * BKB + (cgrp + j) * 16);

    const int NCH = Klen / 64;

#pragma unroll
    for (int c = 0; c < NSTAGE - 1; ++c) {
        const uint32_t sA = sbase + c * STAGE;
        const uint32_t sB = sA + TILE_A;
#pragma unroll
        for (int j = 0; j < 4; ++j) {
            cp16(sA + dstOff[j], aRow + c * 64 + j * 8);
            cp16(sB + dstOff[j], bRow + c * 64 + j * 8);
        }
        cp_commit();
    }

    float acc[4][4][4];
#pragma unroll
    for (int i = 0; i < 4; ++i)
#pragma unroll
        for (int j = 0; j < 4; ++j)
#pragma unroll
            for (int r = 0; r < 4; ++r) acc[i][j][r] = 0.f;

    const int arow = wm * 64 + (lane & 15);
    const uint32_t acolbase = (lane >> 4) << 4;
    const int brow = wn * 32 + ((lane >> 4) << 3) + (lane & 7);
    const uint32_t bcolbase = ((lane >> 3) & 1) << 4;

    for (int c = 0; c < NCH; ++c) {
        cp_wait<NSTAGE - 2>();
        __syncthreads();

        if (c + NSTAGE - 1 < NCH) {
            const int cc = c + NSTAGE - 1;
            const uint32_t sA = sbase + (cc % NSTAGE) * STAGE;
            const uint32_t sB = sA + TILE_A;
#pragma unroll
            for (int j = 0; j < 4; ++j) {
                cp16(sA + dstOff[j], aRow + (size_t)cc * 64 + j * 8);
                cp16(sB + dstOff[j], bRow + (size_t)cc * 64 + j * 8);
            }
        }
        cp_commit();

        const uint32_t sA = sbase + (c % NSTAGE) * STAGE;
        const uint32_t sB = sA + TILE_A;

#pragma unroll
        for (int kk = 0; kk < 4; ++kk) {
            uint32_t af[4][4], bf[2][4];
#pragma unroll
            for (int fm = 0; fm < 4; ++fm) {
                const int r = arow + fm * 16;
                ldsm4(af[fm][0], af[fm][1], af[fm][2], af[fm][3],
                      sA + swz((uint32_t)r * BKB + kk * 32 + acolbase));
            }
#pragma unroll
            for (int fn2 = 0; fn2 < 2; ++fn2) {
                const int r = brow + fn2 * 16;
                ldsm4(bf[fn2][0], bf[fn2][1], bf[fn2][2], bf[fn2][3],
                      sB + swz((uint32_t)r * BKB + kk * 32 + bcolbase));
            }
#pragma unroll
            for (int fm = 0; fm < 4; ++fm)
#pragma unroll
                for (int fn = 0; fn < 4; ++fn)
                    mma_f16(acc[fm][fn], af[fm], &bf[fn >> 1][(fn & 1) * 2]);
        }
    }

#pragma unroll
    for (int fm = 0; fm < 4; ++fm) {
        const int r = m0 + wm * 64 + fm * 16 + (lane >> 2);
#pragma unroll
        for (int fn = 0; fn < 4; ++fn) {
            const int cidx = n0 + wn * 32 + fn * 8 + (lane & 3) * 2;
            const float b0 = bias[cidx], b1 = bias[cidx + 1];
            *(float2*)&Cout[(size_t)r * N + cidx] =
                make_float2(acc[fm][fn][0] + b0, acc[fm][fn][1] + b1);
            *(float2*)&Cout[(size_t)(r + 8) * N + cidx] =
                make_float2(acc[fm][fn][2] + b0, acc[fm][fn][3] + b1);
        }
    }
}

// ---------------------------------------------------------------------------
// Flash attention on mma.sync (unchanged from round 6).
// ---------------------------------------------------------------------------
#define AQHI 0
#define AQLO 16384
#define ASTG 32768
#define STGB 24576
#define ATT_SMEM (ASTG + 2 * STGB + 1024)

__global__ __launch_bounds__(256) void attn_mma_kernel(
    const __nv_bfloat16* __restrict__ Qhi, const __nv_bfloat16* __restrict__ Qlo,
    const __nv_bfloat16* __restrict__ Khi, const __nv_bfloat16* __restrict__ Klo,
    const __half* __restrict__ V, __half* __restrict__ Y2)
{
    extern __shared__ char dsm[];
    const uint32_t dbase = smem_u32(dsm);
    const uint32_t sb = (dbase + 1023) & ~1023u;

    const int tid = threadIdx.x;
    const int lane = tid & 31;
    const int w = tid >> 5;
    const int qt = (int)gridDim.x - 1 - (int)blockIdx.x;
    const int bh = blockIdx.y;

    const size_t headbase = (size_t)bh * TT * HD;
    const __nv_bfloat16* Qhig = Qhi + headbase + (size_t)qt * 128 * HD;
    const __nv_bfloat16* Qlog = Qlo + headbase + (size_t)qt * 128 * HD;
    const __nv_bfloat16* Khig = Khi + headbase;
    const __nv_bfloat16* Klog = Klo + headbase;
    const __half* Vg = V + headbase;

#pragma unroll
    for (int i = 0; i < 4; ++i) {
        const int c = tid + i * 256;
        const int row = c >> 3, cu = c & 7;
        const uint32_t so = swz(row * 128 + cu * 16);
        cp16(sb + AQHI + so, Qhig + row * HD + cu * 8);
        cp16(sb + AQLO + so, Qlog + row * HD + cu * 8);
    }
    {
        const uint32_t stg = sb + ASTG;
#pragma unroll
        for (int i = 0; i < 2; ++i) {
            const int c = tid + i * 256;
            const int row = c >> 3, cu = c & 7;
            const uint32_t so = swz(row * 128 + cu * 16);
            const size_t go = (size_t)row * HD + cu * 8;
            cp16(stg + so, Khig + go);
            cp16(stg + 8192 + so, Klog + go);
            cp16(stg + 16384 + so, Vg + go);
        }
    }
    cp_commit();

    float oc[8][4];
#pragma unroll
    for (int f = 0; f < 8; ++f)
#pragma unroll
        for (int r = 0; r < 4; ++r) oc[f][r] = 0.f;
    float m0 = -1e30f, m1 = -1e30f, l0 = 0.f, l1 = 0.f;

    const uint32_t aBase = (uint32_t)((w * 16 + (lane & 15)) * 128 +
                                      ((lane >> 4) << 4));
    const uint32_t bRow = ((lane >> 4) << 3) + (lane & 7);
    const uint32_t bColB = ((lane >> 3) & 1) << 4;
    const uint32_t vRow = (((lane >> 3) & 1) << 3) + (lane & 7);
    const uint32_t vColB = (lane >> 4) << 4;

    const int nkt = 2 * qt + 2;
    for (int kt = 0; kt < nkt; ++kt) {
        if (kt + 1 < nkt) {
            const uint32_t stg = sb + ASTG + ((kt + 1) & 1) * STGB;
            const size_t kbase = (size_t)(kt + 1) * 64 * HD;
#pragma unroll
            for (int i = 0; i < 2; ++i) {
                const int c = tid + i * 256;
                const int row = c >> 3, cu = c & 7;
                const uint32_t so = swz(row * 128 + cu * 16);
                const size_t go = kbase + (size_t)row * HD + cu * 8;
                cp16(stg + so, Khig + go);
                cp16(stg + 8192 + so, Klog + go);
                cp16(stg + 16384 + so, Vg + go);
            }
        }
        cp_commit();
        cp_wait<1>();
        __syncthreads();

        const uint32_t stg = sb + ASTG + (kt & 1) * STGB;

        float sc[8][4];
#pragma unroll
        for (int f = 0; f < 8; ++f)
#pragma unroll
            for (int r = 0; r < 4; ++r) sc[f][r] = 0.f;

#pragma unroll
        for (int kk = 0; kk < 4; ++kk) {
            uint32_t bk[4][4];
#pragma unroll
            for (int g = 0; g < 4; ++g)
                ldsm4(bk[g][0], bk[g][1], bk[g][2], bk[g][3],
                      stg + swz((g * 16 + bRow) * 128 + kk * 32 + bColB));
            uint32_t aq[4];
            ldsm4(aq[0], aq[1], aq[2], aq[3], sb + AQHI + swz(aBase + kk * 32));
#pragma unroll
            for (int f = 0; f < 8; ++f)
                mma_bf16(sc[f], aq, &bk[f >> 1][(f & 1) * 2]);
            ldsm4(aq[0], aq[1], aq[2], aq[3], sb + AQLO + swz(aBase + kk * 32));
#pragma unroll
            for (int f = 0; f < 8; ++f)
                mma_bf16(sc[f], aq, &bk[f >> 1][(f & 1) * 2]);
        }
#pragma unroll
        for (int kk = 0; kk < 4; ++kk) {
            uint32_t bk[4][4];
#pragma unroll
            for (int g = 0; g < 4; ++g)
                ldsm4(bk[g][0], bk[g][1], bk[g][2], bk[g][3],
                      stg + 8192 +
                          swz((g * 16 + bRow) * 128 + kk * 32 + bColB));
            uint32_t aq[4];
            ldsm4(aq[0], aq[1], aq[2], aq[3], sb + AQHI + swz(aBase + kk * 32));
#pragma unroll
            for (int f = 0; f < 8; ++f)
                mma_bf16(sc[f], aq, &bk[f >> 1][(f & 1) * 2]);
        }

        if (kt >= 2 * qt) {
            const int rq = qt * 128 + w * 16 + (lane >> 2);
#pragma unroll
            for (int f = 0; f < 8; ++f) {
                const int cg = kt * 64 + f * 8 + 2 * (lane & 3);
                if (cg > rq) sc[f][0] = -1e30f;
                if (cg + 1 > rq) sc[f][1] = -1e30f;
                if (cg > rq + 8) sc[f][2] = -1e30f;
                if (cg + 1 > rq + 8) sc[f][3] = -1e30f;
            }
        }

        float mx0 = -1e30f, mx1 = -1e30f;
#pragma unroll
        for (int f = 0; f < 8; ++f) {
            mx0 = fmaxf(mx0, fmaxf(sc[f][0], sc[f][1]));
            mx1 = fmaxf(mx1, fmaxf(sc[f][2], sc[f][3]));
        }
        mx0 = fmaxf(mx0, __shfl_xor_sync(0xffffffffu, mx0, 1));
        mx0 = fmaxf(mx0, __shfl_xor_sync(0xffffffffu, mx0, 2));
        mx1 = fmaxf(mx1, __shfl_xor_sync(0xffffffffu, mx1, 1));
        mx1 = fmaxf(mx1, __shfl_xor_sync(0xffffffffu, mx1, 2));
        const float mn0 = fmaxf(m0, mx0), mn1 = fmaxf(m1, mx1);
        const float al0 = __expf(m0 - mn0), al1 = __expf(m1 - mn1);
        float rs0 = 0.f, rs1 = 0.f;
#pragma unroll
        for (int f = 0; f < 8; ++f) {
            sc[f][0] = __expf(sc[f][0] - mn0);
            sc[f][1] = __expf(sc[f][1] - mn0);
            sc[f][2] = __expf(sc[f][2] - mn1);
            sc[f][3] = __expf(sc[f][3] - mn1);
            rs0 += sc[f][0] + sc[f][1];
            rs1 += sc[f][2] + sc[f][3];
        }
        rs0 += __shfl_xor_sync(0xffffffffu, rs0, 1);
        rs0 += __shfl_xor_sync(0xffffffffu, rs0, 2);
        rs1 += __shfl_xor_sync(0xffffffffu, rs1, 1);
        rs1 += __shfl_xor_sync(0xffffffffu, rs1, 2);
        m0 = mn0; m1 = mn1;
        l0 = l0 * al0 + rs0;
        l1 = l1 * al1 + rs1;
#pragma unroll
        for (int f = 0; f < 8; ++f) {
            oc[f][0] *= al0; oc[f][1] *= al0;
            oc[f][2] *= al1; oc[f][3] *= al1;
        }

        uint32_t pa[4][4];
#pragma unroll
        for (int j = 0; j < 4; ++j) {
            pa[j][0] = packh2(sc[2 * j][0], sc[2 * j][1]);
            pa[j][1] = packh2(sc[2 * j][2], sc[2 * j][3]);
            pa[j][2] = packh2(sc[2 * j + 1][0], sc[2 * j + 1][1]);
            pa[j][3] = packh2(sc[2 * j + 1][2], sc[2 * j + 1][3]);
        }

#pragma unroll
        for (int kb = 0; kb < 4; ++kb) {
            uint32_t bv[4][4];
#pragma unroll
            for (int g = 0; g < 4; ++g)
                ldsm4t(bv[g][0], bv[g][1], bv[g][2], bv[g][3],
                       stg + 16384 +
                           swz((kb * 16 + vRow) * 128 + g * 32 + vColB));
#pragma unroll
            for (int f = 0; f < 8; ++f)
                mma_f16(oc[f], pa[kb], &bv[f >> 1][(f & 1) * 2]);
        }
        __syncthreads();
    }

    const float inv0 = 1.f / l0, inv1 = 1.f / l1;
    const int b = bh >> 4, h = bh & 15;
    const int t0 = qt * 128 + w * 16 + (lane >> 2);
    const size_t mr0 = (size_t)(b * TT + t0) * K2;
    const size_t mr1 = mr0 + (size_t)8 * K2;
#pragma unroll
    for (int f = 0; f < 8; ++f) {
        const int n = h * HD + f * 8 + 2 * (lane & 3);
#pragma unroll
        for (int rr = 0; rr < 2; ++rr) {
            const size_t base = rr ? mr1 : mr0;
            const float va = (rr ? oc[f][2] * inv1 : oc[f][0] * inv0);
            const float vb = (rr ? oc[f][3] * inv1 : oc[f][1] * inv0);
            __half2 hp = __floats2half2_rn(va, vb);
            *(__half2*)&Y2[base + n] = hp;
            *(__half2*)&Y2[base + CC + n] = hp;
        }
    }
}

// ---------------------------------------------------------------------------
// launch
// ---------------------------------------------------------------------------
extern "C" void kernel_launch(void* const* d_in, const int* in_sizes, int n_in,
                              void* d_out, int out_size)
{
    (void)in_sizes; (void)n_in; (void)out_size;
    const float* x      = (const float*)d_in[0];
    const float* W_attn = (const float*)d_in[1];
    const float* b_attn = (const float*)d_in[2];
    const float* W_proj = (const float*)d_in[3];
    const float* b_proj = (const float*)d_in[4];
    float* out = (float*)d_out;

    __nv_bfloat16 *ahi, *alo, *wahi, *walo, *qhi, *qlo, *khi, *klo;
    __half *wp2, *y2, *vh;
    cudaGetSymbolAddress((void**)&ahi, g_ahi);
    cudaGetSymbolAddress((void**)&alo, g_alo);
    cudaGetSymbolAddress((void**)&wahi, g_wahi);
    cudaGetSymbolAddress((void**)&walo, g_walo);
    cudaGetSymbolAddress((void**)&wp2, g_wp2);
    cudaGetSymbolAddress((void**)&y2, g_y2);
    cudaGetSymbolAddress((void**)&qhi, g_qhi);
    cudaGetSymbolAddress((void**)&qlo, g_qlo);
    cudaGetSymbolAddress((void**)&khi, g_khi);
    cudaGetSymbolAddress((void**)&klo, g_klo);
    cudaGetSymbolAddress((void**)&vh, g_v);

    cudaFuncSetAttribute(gemm1_kernel,
                         cudaFuncAttributeMaxDynamicSharedMemorySize,
                         G1_NSTAGE * G1_STAGE);
    cudaFuncSetAttribute(gemm2_kernel,
                         cudaFuncAttributeMaxDynamicSharedMemorySize,
                         NSTAGE * STAGE);
    cudaFuncSetAttribute(attn_mma_kernel,
                         cudaFuncAttributeMaxDynamicSharedMemorySize, ATT_SMEM);

    // 0) splits
    {
        const int n4 = MTOT * CC / 4;
        convert_split2_kernel<<<(n4 + 255) / 256, 256>>>(x, ahi, alo, n4);
        dim3 tb(32, 8);
        dim3 gb(3 * CC / 32, CC / 32);
        transpose_split2_pair_kernel<<<gb, tb>>>(W_attn, wahi, walo, CC,
                                                 3 * CC);
        dim3 gp(CC / 32, CC / 32);
        transpose_split2_f16_kernel<<<gp, tb>>>(W_proj, wp2, CC, CC);
    }
    // 1) QKV GEMM (dedup 3-term bf16 split) -> split Q/K + V, head-major
    {
        dim3 grid(3 * CC / 128, MTOT / 128);  // (24, 32)
        gemm1_kernel<<<grid, 256, G1_NSTAGE * G1_STAGE>>>(
            ahi, alo, wahi, walo, b_attn, qhi, qlo, khi, klo, vh);
    }
    // 2) attention -> writes y fp16 [M][2K]
    {
        dim3 grid(TT / 128, BB * NH);
        attn_mma_kernel<<<grid, 256, ATT_SMEM>>>(qhi, qlo, khi, klo, vh, y2);
    }
    // 3) out = y @ W_proj + b_proj (fp16 2-term)
    {
        dim3 grid(CC / 128, MTOT / 128);  // (8, 32)
        gemm2_kernel<<<grid, 256, NSTAGE * STAGE>>>(y2, wp2, b_proj, out, CC,
                                                    K2);
    }
}

// round 8
// speedup vs baseline: 1.3233x; 1.3233x over previous
#include <cuda_runtime.h>
#include <cuda_bf16.h>
#include <cuda_fp16.h>
#include <cstdint>
#include <cstddef>

// ---------------------------------------------------------------------------
// MultiHeadAttention: x@W_attn+b -> causal MHA -> @W_proj+b
// B=2, T=2048, C=1024, H=16, D=64.
// Round 8: GEMM1 fp16 2-term (A=[x16|x16], B=[Wh|Wl], K'=2048);
// attention split-bf16 QK^T + fp16 PV; GEMM2 fp16 2-term. mma.sync throughout.
// ---------------------------------------------------------------------------

#define BB 2
#define TT 2048
#define CC 1024
#define NH 16
#define HD 64
#define MTOT (BB * TT)  // 4096
#define K2 (2 * CC)     // 2048

// ------------------------------ scratch ------------------------------------
__device__ __half        g_a2[MTOT * K2];         // [M][2K] = [x16 | x16]
__device__ __half        g_wa2[3 * CC * K2];      // W_attn^T [3C][2K]=[Wh|Wl]
__device__ __half        g_wp2[CC * K2];          // W_proj^T [C][2K]=[Wh|Wl]
__device__ __half        g_y2[MTOT * K2];         // y fp16 [M][2K]=[y|y]
__device__ __nv_bfloat16 g_qhi[BB * NH * TT * HD];
__device__ __nv_bfloat16 g_qlo[BB * NH * TT * HD];
__device__ __nv_bfloat16 g_khi[BB * NH * TT * HD];
__device__ __nv_bfloat16 g_klo[BB * NH * TT * HD];
__device__ __half        g_v[BB * NH * TT * HD];

// ------------------------------ helpers ------------------------------------
__device__ __forceinline__ uint32_t smem_u32(const void* p) {
    uint32_t a;
    asm("{ .reg .u64 t; cvta.to.shared.u64 t, %1; cvt.u32.u64 %0, t; }"
        : "=r"(a) : "l"(p));
    return a;
}
__device__ __forceinline__ uint32_t swz(uint32_t x) {  // SW128 (128B rows)
    return x ^ ((x >> 3) & 0x70);
}
__device__ __forceinline__ void cp16(uint32_t dst, const void* src) {
    asm volatile("cp.async.cg.shared.global [%0], [%1], 16;"
                 :: "r"(dst), "l"(src));
}
__device__ __forceinline__ void cp_commit() {
    asm volatile("cp.async.commit_group;");
}
template <int N>
__device__ __forceinline__ void cp_wait() {
    asm volatile("cp.async.wait_group %0;" :: "n"(N));
}
__device__ __forceinline__ void ldsm4(uint32_t& r0, uint32_t& r1, uint32_t& r2,
                                      uint32_t& r3, uint32_t addr) {
    asm volatile("ldmatrix.sync.aligned.m8n8.x4.shared.b16 {%0,%1,%2,%3}, [%4];"
                 : "=r"(r0), "=r"(r1), "=r"(r2), "=r"(r3) : "r"(addr));
}
__device__ __forceinline__ void ldsm4t(uint32_t& r0, uint32_t& r1, uint32_t& r2,
                                       uint32_t& r3, uint32_t addr) {
    asm volatile(
        "ldmatrix.sync.aligned.m8n8.x4.trans.shared.b16 {%0,%1,%2,%3}, [%4];"
        : "=r"(r0), "=r"(r1), "=r"(r2), "=r"(r3) : "r"(addr));
}
__device__ __forceinline__ void mma_bf16(float* c, const uint32_t* a,
                                         const uint32_t* b) {
    asm volatile(
        "mma.sync.aligned.m16n8k16.row.col.f32.bf16.bf16.f32 "
        "{%0,%1,%2,%3}, {%4,%5,%6,%7}, {%8,%9}, {%0,%1,%2,%3};"
        : "+f"(c[0]), "+f"(c[1]), "+f"(c[2]), "+f"(c[3])
        : "r"(a[0]), "r"(a[1]), "r"(a[2]), "r"(a[3]), "r"(b[0]), "r"(b[1]));
}
__device__ __forceinline__ void mma_f16(float* c, const uint32_t* a,
                                        const uint32_t* b) {
    asm volatile(
        "mma.sync.aligned.m16n8k16.row.col.f32.f16.f16.f32 "
        "{%0,%1,%2,%3}, {%4,%5,%6,%7}, {%8,%9}, {%0,%1,%2,%3};"
        : "+f"(c[0]), "+f"(c[1]), "+f"(c[2]), "+f"(c[3])
        : "r"(a[0]), "r"(a[1]), "r"(a[2]), "r"(a[3]), "r"(b[0]), "r"(b[1]));
}
__device__ __forceinline__ uint32_t packh2(float a, float b) {
    __half2 h = __floats2half2_rn(a, b);
    return *reinterpret_cast<uint32_t*>(&h);
}

// ---------------------------------------------------------------------------
// convert_dup_f16: X [M][K] fp32 -> A2 [M][2K] fp16 = [x16 | x16]
// ---------------------------------------------------------------------------
__global__ __launch_bounds__(256) void convert_dup_f16_kernel(
    const float* __restrict__ X, __half* __restrict__ A2, int n4)
{
    int i = blockIdx.x * blockDim.x + threadIdx.x;
    if (i >= n4) return;
    const int m = i >> 8;             // K/4 = 256
    const int kk = (i & 255) << 2;
    float4 v = ((const float4*)X)[i];
    __half2 h0 = __floats2half2_rn(v.x, v.y);
    __half2 h1 = __floats2half2_rn(v.z, v.w);
    __half2* p0 = (__half2*)(A2 + (size_t)m * K2 + kk);
    p0[0] = h0; p0[1] = h1;
    __half2* p1 = (__half2*)(A2 + (size_t)m * K2 + CC + kk);
    p1[0] = h0; p1[1] = h1;
}

// ---------------------------------------------------------------------------
// transpose_split2_f16: W [K][N] fp32 -> B2 [N][2K] fp16 = [Wh | Wl]
// ---------------------------------------------------------------------------
__global__ __launch_bounds__(256) void transpose_split2_f16_kernel(
    const float* __restrict__ W, __half* __restrict__ B2, int K, int N)
{
    __shared__ float t[32][33];
    const int n0 = blockIdx.x * 32, k0 = blockIdx.y * 32;
    const int tx = threadIdx.x, ty = threadIdx.y;
#pragma unroll
    for (int i = 0; i < 32; i += 8)
        t[ty + i][tx] = W[(size_t)(k0 + ty + i) * N + n0 + tx];
    __syncthreads();
#pragma unroll
    for (int i = 0; i < 32; i += 8) {
        const int n = n0 + ty + i, k = k0 + tx;
        const float v = t[tx][ty + i];
        const __half h = __float2half_rn(v);
        __half* row = B2 + (size_t)n * (2 * K);
        row[k] = h;
        row[K + k] = __float2half_rn(v - __half2float(h));
    }
}

// ---------------------------------------------------------------------------
// fp16 mma.sync GEMM: C = A @ B^T (+bias). K'=2048, CTA 128x128, BK=64,
// 3 stages, 2 CTA/SM, 8 warps (2x4), warp 64x32.
// EPI=0: fp32 out + bias. EPI=1: QKV epilogue -> split Q/K bf16 + V fp16,
//        head-major, Q pre-scaled by 0.125.
// ---------------------------------------------------------------------------
#define BKB 128
#define TILE_A 16384
#define STAGE 32768
#define NSTAGE 3
#define NCH (K2 / 64)  // 32

template <int EPI>
__global__ __launch_bounds__(256, 2) void gemm_f16_kernel(
    const __half* __restrict__ A, const __half* __restrict__ B,
    const float* __restrict__ bias, float* __restrict__ Cout,
    __nv_bfloat16* __restrict__ Qhi, __nv_bfloat16* __restrict__ Qlo,
    __nv_bfloat16* __restrict__ Khi, __nv_bfloat16* __restrict__ Klo,
    __half* __restrict__ Vh, int N)
{
    extern __shared__ char dsm[];
    const uint32_t sbase = smem_u32(dsm);

    const int tid = threadIdx.x;
    const int lane = tid & 31;
    const int warp = tid >> 5;
    const int wm = warp >> 2;
    const int wn = warp & 3;
    const int n0 = blockIdx.x * 128;
    const int m0 = blockIdx.y * 128;

    const int ldrow = tid >> 1;
    const int cgrp = (tid & 1) * 4;
    const __half* aRow = A + (size_t)(m0 + ldrow) * K2 + cgrp * 8;
    const __half* bRow = B + (size_t)(n0 + ldrow) * K2 + cgrp * 8;
    uint32_t dstOff[4];
#pragma unroll
    for (int j = 0; j < 4; ++j)
        dstOff[j] = swz(ldrow * BKB + (cgrp + j) * 16);

#pragma unroll
    for (int c = 0; c < NSTAGE - 1; ++c) {
        const uint32_t sA = sbase + c * STAGE;
        const uint32_t sB = sA + TILE_A;
#pragma unroll
        for (int j = 0; j < 4; ++j) {
            cp16(sA + dstOff[j], aRow + c * 64 + j * 8);
            cp16(sB + dstOff[j], bRow + c * 64 + j * 8);
        }
        cp_commit();
    }

    float acc[4][4][4];
#pragma unroll
    for (int i = 0; i < 4; ++i)
#pragma unroll
        for (int j = 0; j < 4; ++j)
#pragma unroll
            for (int r = 0; r < 4; ++r) acc[i][j][r] = 0.f;

    const int arow = wm * 64 + (lane & 15);
    const uint32_t acolbase = (lane >> 4) << 4;
    const int brow = wn * 32 + ((lane >> 4) << 3) + (lane & 7);
    const uint32_t bcolbase = ((lane >> 3) & 1) << 4;

    for (int c = 0; c < NCH; ++c) {
        cp_wait<NSTAGE - 2>();
        __syncthreads();

        if (c + NSTAGE - 1 < NCH) {
            const int cc = c + NSTAGE - 1;
            const uint32_t sA = sbase + (cc % NSTAGE) * STAGE;
            const uint32_t sB = sA + TILE_A;
#pragma unroll
            for (int j = 0; j < 4; ++j) {
                cp16(sA + dstOff[j], aRow + (size_t)cc * 64 + j * 8);
                cp16(sB + dstOff[j], bRow + (size_t)cc * 64 + j * 8);
            }
        }
        cp_commit();

        const uint32_t sA = sbase + (c % NSTAGE) * STAGE;
        const uint32_t sB = sA + TILE_A;

#pragma unroll
        for (int kk = 0; kk < 4; ++kk) {
            uint32_t af[4][4], bf[2][4];
#pragma unroll
            for (int fm = 0; fm < 4; ++fm) {
                const int r = arow + fm * 16;
                ldsm4(af[fm][0], af[fm][1], af[fm][2], af[fm][3],
                      sA + swz((uint32_t)r * BKB + kk * 32 + acolbase));
            }
#pragma unroll
            for (int fn2 = 0; fn2 < 2; ++fn2) {
                const int r = brow + fn2 * 16;
                ldsm4(bf[fn2][0], bf[fn2][1], bf[fn2][2], bf[fn2][3],
                      sB + swz((uint32_t)r * BKB + kk * 32 + bcolbase));
            }
#pragma unroll
            for (int fm = 0; fm < 4; ++fm)
#pragma unroll
                for (int fn = 0; fn < 4; ++fn)
                    mma_f16(acc[fm][fn], af[fm], &bf[fn >> 1][(fn & 1) * 2]);
        }
        __syncthreads();
    }

    // epilogue
#pragma unroll
    for (int fm = 0; fm < 4; ++fm) {
        const int r0 = m0 + wm * 64 + fm * 16 + (lane >> 2);
#pragma unroll
        for (int fn = 0; fn < 4; ++fn) {
            const int cidx = n0 + wn * 32 + fn * 8 + (lane & 3) * 2;
            const float b0 = bias[cidx], b1 = bias[cidx + 1];
            float v00 = acc[fm][fn][0] + b0, v01 = acc[fm][fn][1] + b1;
            float v10 = acc[fm][fn][2] + b0, v11 = acc[fm][fn][3] + b1;
            if (EPI == 0) {
                *(float2*)&Cout[(size_t)r0 * N + cidx] = make_float2(v00, v01);
                *(float2*)&Cout[(size_t)(r0 + 8) * N + cidx] =
                    make_float2(v10, v11);
            } else {
                const int reg = cidx >> 10;
                const int idx = cidx & 1023;
                const int h = idx >> 6, d = idx & 63;
#pragma unroll
                for (int rr = 0; rr < 2; ++rr) {
                    const int m = r0 + rr * 8;
                    const int bb = m >> 11, t = m & 2047;
                    float va = rr ? v10 : v00;
                    float vb = rr ? v11 : v01;
                    const size_t off =
                        ((size_t)(bb * NH + h) * TT + t) * HD + d;
                    if (reg == 0) {
                        va *= 0.125f; vb *= 0.125f;
                        __nv_bfloat16 ha = __float2bfloat16(va);
                        __nv_bfloat16 hb = __float2bfloat16(vb);
                        *(__nv_bfloat162*)&Qhi[off] = __nv_bfloat162(ha, hb);
                        *(__nv_bfloat162*)&Qlo[off] = __nv_bfloat162(
                            __float2bfloat16(va - __bfloat162float(ha)),
                            __float2bfloat16(vb - __bfloat162float(hb)));
                    } else if (reg == 1) {
                        __nv_bfloat16 ha = __float2bfloat16(va);
                        __nv_bfloat16 hb = __float2bfloat16(vb);
                        *(__nv_bfloat162*)&Khi[off] = __nv_bfloat162(ha, hb);
                        *(__nv_bfloat162*)&Klo[off] = __nv_bfloat162(
                            __float2bfloat16(va - __bfloat162float(ha)),
                            __float2bfloat16(vb - __bfloat162float(hb)));
                    } else {
                        *(__half2*)&Vh[off] = __floats2half2_rn(va, vb);
                    }
                }
            }
        }
    }
}

// ---------------------------------------------------------------------------
// Flash attention on mma.sync (unchanged from round 6).
// ---------------------------------------------------------------------------
#define AQHI 0
#define AQLO 16384
#define ASTG 32768
#define STGB 24576
#define ATT_SMEM (ASTG + 2 * STGB + 1024)

__global__ __launch_bounds__(256) void attn_mma_kernel(
    const __nv_bfloat16* __restrict__ Qhi, const __nv_bfloat16* __restrict__ Qlo,
    const __nv_bfloat16* __restrict__ Khi, const __nv_bfloat16* __restrict__ Klo,
    const __half* __restrict__ V, __half* __restrict__ Y2)
{
    extern __shared__ char dsm[];
    const uint32_t dbase = smem_u32(dsm);
    const uint32_t sb = (dbase + 1023) & ~1023u;

    const int tid = threadIdx.x;
    const int lane = tid & 31;
    const int w = tid >> 5;
    const int qt = (int)gridDim.x - 1 - (int)blockIdx.x;
    const int bh = blockIdx.y;

    const size_t headbase = (size_t)bh * TT * HD;
    const __nv_bfloat16* Qhig = Qhi + headbase + (size_t)qt * 128 * HD;
    const __nv_bfloat16* Qlog = Qlo + headbase + (size_t)qt * 128 * HD;
    const __nv_bfloat16* Khig = Khi + headbase;
    const __nv_bfloat16* Klog = Klo + headbase;
    const __half* Vg = V + headbase;

#pragma unroll
    for (int i = 0; i < 4; ++i) {
        const int c = tid + i * 256;
        const int row = c >> 3, cu = c & 7;
        const uint32_t so = swz(row * 128 + cu * 16);
        cp16(sb + AQHI + so, Qhig + row * HD + cu * 8);
        cp16(sb + AQLO + so, Qlog + row * HD + cu * 8);
    }
    {
        const uint32_t stg = sb + ASTG;
#pragma unroll
        for (int i = 0; i < 2; ++i) {
            const int c = tid + i * 256;
            const int row = c >> 3, cu = c & 7;
            const uint32_t so = swz(row * 128 + cu * 16);
            const size_t go = (size_t)row * HD + cu * 8;
            cp16(stg + so, Khig + go);
            cp16(stg + 8192 + so, Klog + go);
            cp16(stg + 16384 + so, Vg + go);
        }
    }
    cp_commit();

    float oc[8][4];
#pragma unroll
    for (int f = 0; f < 8; ++f)
#pragma unroll
        for (int r = 0; r < 4; ++r) oc[f][r] = 0.f;
    float m0 = -1e30f, m1 = -1e30f, l0 = 0.f, l1 = 0.f;

    const uint32_t aBase = (uint32_t)((w * 16 + (lane & 15)) * 128 +
                                      ((lane >> 4) << 4));
    const uint32_t bRow = ((lane >> 4) << 3) + (lane & 7);
    const uint32_t bColB = ((lane >> 3) & 1) << 4;
    const uint32_t vRow = (((lane >> 3) & 1) << 3) + (lane & 7);
    const uint32_t vColB = (lane >> 4) << 4;

    const int nkt = 2 * qt + 2;
    for (int kt = 0; kt < nkt; ++kt) {
        if (kt + 1 < nkt) {
            const uint32_t stg = sb + ASTG + ((kt + 1) & 1) * STGB;
            const size_t kbase = (size_t)(kt + 1) * 64 * HD;
#pragma unroll
            for (int i = 0; i < 2; ++i) {
                const int c = tid + i * 256;
                const int row = c >> 3, cu = c & 7;
                const uint32_t so = swz(row * 128 + cu * 16);
                const size_t go = kbase + (size_t)row * HD + cu * 8;
                cp16(stg + so, Khig + go);
                cp16(stg + 8192 + so, Klog + go);
                cp16(stg + 16384 + so, Vg + go);
            }
        }
        cp_commit();
        cp_wait<1>();
        __syncthreads();

        const uint32_t stg = sb + ASTG + (kt & 1) * STGB;

        float sc[8][4];
#pragma unroll
        for (int f = 0; f < 8; ++f)
#pragma unroll
            for (int r = 0; r < 4; ++r) sc[f][r] = 0.f;

#pragma unroll
        for (int kk = 0; kk < 4; ++kk) {
            uint32_t bk[4][4];
#pragma unroll
            for (int g = 0; g < 4; ++g)
                ldsm4(bk[g][0], bk[g][1], bk[g][2], bk[g][3],
                      stg + swz((g * 16 + bRow) * 128 + kk * 32 + bColB));
            uint32_t aq[4];
            ldsm4(aq[0], aq[1], aq[2], aq[3], sb + AQHI + swz(aBase + kk * 32));
#pragma unroll
            for (int f = 0; f < 8; ++f)
                mma_bf16(sc[f], aq, &bk[f >> 1][(f & 1) * 2]);
            ldsm4(aq[0], aq[1], aq[2], aq[3], sb + AQLO + swz(aBase + kk * 32));
#pragma unroll
            for (int f = 0; f < 8; ++f)
                mma_bf16(sc[f], aq, &bk[f >> 1][(f & 1) * 2]);
        }
#pragma unroll
        for (int kk = 0; kk < 4; ++kk) {
            uint32_t bk[4][4];
#pragma unroll
            for (int g = 0; g < 4; ++g)
                ldsm4(bk[g][0], bk[g][1], bk[g][2], bk[g][3],
                      stg + 8192 +
                          swz((g * 16 + bRow) * 128 + kk * 32 + bColB));
            uint32_t aq[4];
            ldsm4(aq[0], aq[1], aq[2], aq[3], sb + AQHI + swz(aBase + kk * 32));
#pragma unroll
            for (int f = 0; f < 8; ++f)
                mma_bf16(sc[f], aq, &bk[f >> 1][(f & 1) * 2]);
        }

        if (kt >= 2 * qt) {
            const int rq = qt * 128 + w * 16 + (lane >> 2);
#pragma unroll
            for (int f = 0; f < 8; ++f) {
                const int cg = kt * 64 + f * 8 + 2 * (lane & 3);
                if (cg > rq) sc[f][0] = -1e30f;
                if (cg + 1 > rq) sc[f][1] = -1e30f;
                if (cg > rq + 8) sc[f][2] = -1e30f;
                if (cg + 1 > rq + 8) sc[f][3] = -1e30f;
            }
        }

        float mx0 = -1e30f, mx1 = -1e30f;
#pragma unroll
        for (int f = 0; f < 8; ++f) {
            mx0 = fmaxf(mx0, fmaxf(sc[f][0], sc[f][1]));
            mx1 = fmaxf(mx1, fmaxf(sc[f][2], sc[f][3]));
        }
        mx0 = fmaxf(mx0, __shfl_xor_sync(0xffffffffu, mx0, 1));
        mx0 = fmaxf(mx0, __shfl_xor_sync(0xffffffffu, mx0, 2));
        mx1 = fmaxf(mx1, __shfl_xor_sync(0xffffffffu, mx1, 1));
        mx1 = fmaxf(mx1, __shfl_xor_sync(0xffffffffu, mx1, 2));
        const float mn0 = fmaxf(m0, mx0), mn1 = fmaxf(m1, mx1);
        const float al0 = __expf(m0 - mn0), al1 = __expf(m1 - mn1);
        float rs0 = 0.f, rs1 = 0.f;
#pragma unroll
        for (int f = 0; f < 8; ++f) {
            sc[f][0] = __expf(sc[f][0] - mn0);
            sc[f][1] = __expf(sc[f][1] - mn0);
            sc[f][2] = __expf(sc[f][2] - mn1);
            sc[f][3] = __expf(sc[f][3] - mn1);
            rs0 += sc[f][0] + sc[f][1];
            rs1 += sc[f][2] + sc[f][3];
        }
        rs0 += __shfl_xor_sync(0xffffffffu, rs0, 1);
        rs0 += __shfl_xor_sync(0xffffffffu, rs0, 2);
        rs1 += __shfl_xor_sync(0xffffffffu, rs1, 1);
        rs1 += __shfl_xor_sync(0xffffffffu, rs1, 2);
        m0 = mn0; m1 = mn1;
        l0 = l0 * al0 + rs0;
        l1 = l1 * al1 + rs1;
#pragma unroll
        for (int f = 0; f < 8; ++f) {
            oc[f][0] *= al0; oc[f][1] *= al0;
            oc[f][2] *= al1; oc[f][3] *= al1;
        }

        uint32_t pa[4][4];
#pragma unroll
        for (int j = 0; j < 4; ++j) {
            pa[j][0] = packh2(sc[2 * j][0], sc[2 * j][1]);
            pa[j][1] = packh2(sc[2 * j][2], sc[2 * j][3]);
            pa[j][2] = packh2(sc[2 * j + 1][0], sc[2 * j + 1][1]);
            pa[j][3] = packh2(sc[2 * j + 1][2], sc[2 * j + 1][3]);
        }

#pragma unroll
        for (int kb = 0; kb < 4; ++kb) {
            uint32_t bv[4][4];
#pragma unroll
            for (int g = 0; g < 4; ++g)
                ldsm4t(bv[g][0], bv[g][1], bv[g][2], bv[g][3],
                       stg + 16384 +
                           swz((kb * 16 + vRow) * 128 + g * 32 + vColB));
#pragma unroll
            for (int f = 0; f < 8; ++f)
                mma_f16(oc[f], pa[kb], &bv[f >> 1][(f & 1) * 2]);
        }
        __syncthreads();
    }

    const float inv0 = 1.f / l0, inv1 = 1.f / l1;
    const int b = bh >> 4, h = bh & 15;
    const int t0 = qt * 128 + w * 16 + (lane >> 2);
    const size_t mr0 = (size_t)(b * TT + t0) * K2;
    const size_t mr1 = mr0 + (size_t)8 * K2;
#pragma unroll
    for (int f = 0; f < 8; ++f) {
        const int n = h * HD + f * 8 + 2 * (lane & 3);
#pragma unroll
        for (int rr = 0; rr < 2; ++rr) {
            const size_t base = rr ? mr1 : mr0;
            const float va = (rr ? oc[f][2] * inv1 : oc[f][0] * inv0);
            const float vb = (rr ? oc[f][3] * inv1 : oc[f][1] * inv0);
            __half2 hp = __floats2half2_rn(va, vb);
            *(__half2*)&Y2[base + n] = hp;
            *(__half2*)&Y2[base + CC + n] = hp;
        }
    }
}

// ---------------------------------------------------------------------------
// launch
// ---------------------------------------------------------------------------
extern "C" void kernel_launch(void* const* d_in, const int* in_sizes, int n_in,
                              void* d_out, int out_size)
{
    (void)in_sizes; (void)n_in; (void)out_size;
    const float* x      = (const float*)d_in[0];
    const float* W_attn = (const float*)d_in[1];
    const float* b_attn = (const float*)d_in[2];
    const float* W_proj = (const float*)d_in[3];
    const float* b_proj = (const float*)d_in[4];
    float* out = (float*)d_out;

    __nv_bfloat16 *qhi, *qlo, *khi, *klo;
    __half *a2, *wa2, *wp2, *y2, *vh;
    cudaGetSymbolAddress((void**)&a2, g_a2);
    cudaGetSymbolAddress((void**)&wa2, g_wa2);
    cudaGetSymbolAddress((void**)&wp2, g_wp2);
    cudaGetSymbolAddress((void**)&y2, g_y2);
    cudaGetSymbolAddress((void**)&qhi, g_qhi);
    cudaGetSymbolAddress((void**)&qlo, g_qlo);
    cudaGetSymbolAddress((void**)&khi, g_khi);
    cudaGetSymbolAddress((void**)&klo, g_klo);
    cudaGetSymbolAddress((void**)&vh, g_v);

    cudaFuncSetAttribute(gemm_f16_kernel<1>,
                         cudaFuncAttributeMaxDynamicSharedMemorySize,
                         NSTAGE * STAGE);
    cudaFuncSetAttribute(gemm_f16_kernel<0>,
                         cudaFuncAttributeMaxDynamicSharedMemorySize,
                         NSTAGE * STAGE);
    cudaFuncSetAttribute(attn_mma_kernel,
                         cudaFuncAttributeMaxDynamicSharedMemorySize, ATT_SMEM);

    // 0) converts
    {
        const int n4 = MTOT * CC / 4;
        convert_dup_f16_kernel<<<(n4 + 255) / 256, 256>>>(x, a2, n4);
        dim3 tb(32, 8);
        dim3 gb(3 * CC / 32, CC / 32);
        transpose_split2_f16_kernel<<<gb, tb>>>(W_attn, wa2, CC, 3 * CC);
        dim3 gp(CC / 32, CC / 32);
        transpose_split2_f16_kernel<<<gp, tb>>>(W_proj, wp2, CC, CC);
    }
    // 1) QKV GEMM (fp16 2-term) -> split Q/K bf16 + V fp16, head-major
    {
        dim3 grid(3 * CC / 128, MTOT / 128);  // (24, 32)
        gemm_f16_kernel<1><<<grid, 256, NSTAGE * STAGE>>>(
            a2, wa2, b_attn, nullptr, qhi, qlo, khi, klo, vh, 3 * CC);
    }
    // 2) attention -> writes y fp16 [M][2K]
    {
        dim3 grid(TT / 128, BB * NH);
        attn_mma_kernel<<<grid, 256, ATT_SMEM>>>(qhi, qlo, khi, klo, vh, y2);
    }
    // 3) out = y @ W_proj + b_proj (fp16 2-term)
    {
        dim3 grid(CC / 128, MTOT / 128);  // (8, 32)
        gemm_f16_kernel<0><<<grid, 256, NSTAGE * STAGE>>>(
            y2, wp2, b_proj, out, nullptr, nullptr, nullptr, nullptr, nullptr,
            CC);
    }
}

// round 9
// speedup vs baseline: 1.5275x; 1.1543x over previous
#include <cuda_runtime.h>
#include <cuda_bf16.h>
#include <cuda_fp16.h>
#include <cstdint>
#include <cstddef>

// ---------------------------------------------------------------------------
// MultiHeadAttention: x@W_attn+b -> causal MHA -> @W_proj+b
// B=2, T=2048, C=1024, H=16, D=64.
// Round 9: all-fp16 mma.sync. GEMM1: x16 @ [Wh|Wl] 2-term (V cols 1-term,
// K'=1024); attention: (Qhi+Qlo fp16) K16^T 2-term + fp16 PV; GEMM2: y16 @
// [Wh|Wl] 2-term. A planes stored once, K-folded in the loader.
// ---------------------------------------------------------------------------

#define BB 2
#define TT 2048
#define CC 1024
#define NH 16
#define HD 64
#define MTOT (BB * TT)  // 4096
#define K2 (2 * CC)     // 2048

// ------------------------------ scratch ------------------------------------
__device__ __half g_x16[MTOT * CC];        // x fp16 (single plane)
__device__ __half g_wa2[3 * CC * K2];      // W_attn^T [3C][2K]=[Wh|Wl]
__device__ __half g_wp2[CC * K2];          // W_proj^T [C][2K]=[Wh|Wl]
__device__ __half g_y16[MTOT * CC];        // y fp16 (single plane)
__device__ __half g_qhi[BB * NH * TT * HD];  // Q/8 fp16 hi/lo (exact split)
__device__ __half g_qlo[BB * NH * TT * HD];
__device__ __half g_k16[BB * NH * TT * HD];  // K fp16 single
__device__ __half g_v[BB * NH * TT * HD];    // V fp16

// ------------------------------ helpers ------------------------------------
__device__ __forceinline__ uint32_t smem_u32(const void* p) {
    uint32_t a;
    asm("{ .reg .u64 t; cvta.to.shared.u64 t, %1; cvt.u32.u64 %0, t; }"
        : "=r"(a) : "l"(p));
    return a;
}
__device__ __forceinline__ uint32_t swz(uint32_t x) {  // SW128 (128B rows)
    return x ^ ((x >> 3) & 0x70);
}
__device__ __forceinline__ void cp16(uint32_t dst, const void* src) {
    asm volatile("cp.async.cg.shared.global [%0], [%1], 16;"
                 :: "r"(dst), "l"(src));
}
__device__ __forceinline__ void cp_commit() {
    asm volatile("cp.async.commit_group;");
}
template <int N>
__device__ __forceinline__ void cp_wait() {
    asm volatile("cp.async.wait_group %0;" :: "n"(N));
}
__device__ __forceinline__ void ldsm4(uint32_t& r0, uint32_t& r1, uint32_t& r2,
                                      uint32_t& r3, uint32_t addr) {
    asm volatile("ldmatrix.sync.aligned.m8n8.x4.shared.b16 {%0,%1,%2,%3}, [%4];"
                 : "=r"(r0), "=r"(r1), "=r"(r2), "=r"(r3) : "r"(addr));
}
__device__ __forceinline__ void ldsm4t(uint32_t& r0, uint32_t& r1, uint32_t& r2,
                                       uint32_t& r3, uint32_t addr) {
    asm volatile(
        "ldmatrix.sync.aligned.m8n8.x4.trans.shared.b16 {%0,%1,%2,%3}, [%4];"
        : "=r"(r0), "=r"(r1), "=r"(r2), "=r"(r3) : "r"(addr));
}
__device__ __forceinline__ void mma_f16(float* c, const uint32_t* a,
                                        const uint32_t* b) {
    asm volatile(
        "mma.sync.aligned.m16n8k16.row.col.f32.f16.f16.f32 "
        "{%0,%1,%2,%3}, {%4,%5,%6,%7}, {%8,%9}, {%0,%1,%2,%3};"
        : "+f"(c[0]), "+f"(c[1]), "+f"(c[2]), "+f"(c[3])
        : "r"(a[0]), "r"(a[1]), "r"(a[2]), "r"(a[3]), "r"(b[0]), "r"(b[1]));
}
__device__ __forceinline__ uint32_t packh2(float a, float b) {
    __half2 h = __floats2half2_rn(a, b);
    return *reinterpret_cast<uint32_t*>(&h);
}

// ---------------------------------------------------------------------------
// convert_f16: X fp32 -> fp16 (single plane)
// ---------------------------------------------------------------------------
__global__ __launch_bounds__(256) void convert_f16_kernel(
    const float* __restrict__ X, __half* __restrict__ O, int n4)
{
    int i = blockIdx.x * blockDim.x + threadIdx.x;
    if (i >= n4) return;
    float4 v = ((const float4*)X)[i];
    ((__half2*)O)[i * 2 + 0] = __floats2half2_rn(v.x, v.y);
    ((__half2*)O)[i * 2 + 1] = __floats2half2_rn(v.z, v.w);
}

// ---------------------------------------------------------------------------
// transpose_split2_f16: W [K][N] fp32 -> B2 [N][2K] fp16 = [Wh | Wl]
// ---------------------------------------------------------------------------
__global__ __launch_bounds__(256) void transpose_split2_f16_kernel(
    const float* __restrict__ W, __half* __restrict__ B2, int K, int N)
{
    __shared__ float t[32][33];
    const int n0 = blockIdx.x * 32, k0 = blockIdx.y * 32;
    const int tx = threadIdx.x, ty = threadIdx.y;
#pragma unroll
    for (int i = 0; i < 32; i += 8)
        t[ty + i][tx] = W[(size_t)(k0 + ty + i) * N + n0 + tx];
    __syncthreads();
#pragma unroll
    for (int i = 0; i < 32; i += 8) {
        const int n = n0 + ty + i, k = k0 + tx;
        const float v = t[tx][ty + i];
        const __half h = __float2half_rn(v);
        __half* row = B2 + (size_t)n * (2 * K);
        row[k] = h;
        row[K + k] = __float2half_rn(v - __half2float(h));
    }
}

// ---------------------------------------------------------------------------
// fp16 mma.sync GEMM: C = A16 @ B2^T (+bias), B2=[Wh|Wl], A folded (k & 1023).
// CTA 128x128, BK=64, 3 stages, 2 CTA/SM, 8 warps (2x4), warp 64x32.
// EPI=0: fp32 out + bias (NCH=32 everywhere).
// EPI=1: QKV epilogue; V column tiles (n0>=2048) use NCH=16 (single term).
// ---------------------------------------------------------------------------
#define BKB 128
#define TILE_A 16384
#define STAGE 32768
#define NSTAGE 3

template <int EPI>
__global__ __launch_bounds__(256, 2) void gemm_f16_kernel(
    const __half* __restrict__ A, const __half* __restrict__ B,
    const float* __restrict__ bias, float* __restrict__ Cout,
    __half* __restrict__ Qhi, __half* __restrict__ Qlo,
    __half* __restrict__ K16, __half* __restrict__ Vh, int N)
{
    extern __shared__ char dsm[];
    const uint32_t sbase = smem_u32(dsm);

    const int tid = threadIdx.x;
    const int lane = tid & 31;
    const int warp = tid >> 5;
    const int wm = warp >> 2;
    const int wn = warp & 3;
    const int n0 = blockIdx.x * 128;
    const int m0 = blockIdx.y * 128;

    const int NCH = (EPI == 1 && n0 >= 2048) ? 16 : 32;

    const int ldrow = tid >> 1;
    const int cgrp = (tid & 1) * 4;
    const __half* aRow = A + (size_t)(m0 + ldrow) * CC + cgrp * 8;
    const __half* bRow = B + (size_t)(n0 + ldrow) * K2 + cgrp * 8;
    uint32_t dstOff[4];
#pragma unroll
    for (int j = 0; j < 4; ++j)
        dstOff[j] = swz(ldrow * BKB + (cgrp + j) * 16);

#pragma unroll
    for (int c = 0; c < NSTAGE - 1; ++c) {
        const uint32_t sA = sbase + c * STAGE;
        const uint32_t sB = sA + TILE_A;
#pragma unroll
        for (int j = 0; j < 4; ++j) {
            cp16(sA + dstOff[j], aRow + (c & 15) * 64 + j * 8);
            cp16(sB + dstOff[j], bRow + c * 64 + j * 8);
        }
        cp_commit();
    }

    float acc[4][4][4];
#pragma unroll
    for (int i = 0; i < 4; ++i)
#pragma unroll
        for (int j = 0; j < 4; ++j)
#pragma unroll
            for (int r = 0; r < 4; ++r) acc[i][j][r] = 0.f;

    const int arow = wm * 64 + (lane & 15);
    const uint32_t acolbase = (lane >> 4) << 4;
    const int brow = wn * 32 + ((lane >> 4) << 3) + (lane & 7);
    const uint32_t bcolbase = ((lane >> 3) & 1) << 4;

    for (int c = 0; c < NCH; ++c) {
        cp_wait<NSTAGE - 2>();
        __syncthreads();

        if (c + NSTAGE - 1 < NCH) {
            const int cc = c + NSTAGE - 1;
            const uint32_t sA = sbase + (cc % NSTAGE) * STAGE;
            const uint32_t sB = sA + TILE_A;
#pragma unroll
            for (int j = 0; j < 4; ++j) {
                cp16(sA + dstOff[j], aRow + (cc & 15) * 64 + j * 8);
                cp16(sB + dstOff[j], bRow + (size_t)cc * 64 + j * 8);
            }
        }
        cp_commit();

        const uint32_t sA = sbase + (c % NSTAGE) * STAGE;
        const uint32_t sB = sA + TILE_A;

#pragma unroll
        for (int kk = 0; kk < 4; ++kk) {
            uint32_t af[4][4], bf[2][4];
#pragma unroll
            for (int fm = 0; fm < 4; ++fm) {
                const int r = arow + fm * 16;
                ldsm4(af[fm][0], af[fm][1], af[fm][2], af[fm][3],
                      sA + swz((uint32_t)r * BKB + kk * 32 + acolbase));
            }
#pragma unroll
            for (int fn2 = 0; fn2 < 2; ++fn2) {
                const int r = brow + fn2 * 16;
                ldsm4(bf[fn2][0], bf[fn2][1], bf[fn2][2], bf[fn2][3],
                      sB + swz((uint32_t)r * BKB + kk * 32 + bcolbase));
            }
#pragma unroll
            for (int fm = 0; fm < 4; ++fm)
#pragma unroll
                for (int fn = 0; fn < 4; ++fn)
                    mma_f16(acc[fm][fn], af[fm], &bf[fn >> 1][(fn & 1) * 2]);
        }
        __syncthreads();
    }

    // epilogue
#pragma unroll
    for (int fm = 0; fm < 4; ++fm) {
        const int r0 = m0 + wm * 64 + fm * 16 + (lane >> 2);
#pragma unroll
        for (int fn = 0; fn < 4; ++fn) {
            const int cidx = n0 + wn * 32 + fn * 8 + (lane & 3) * 2;
            const float b0 = bias[cidx], b1 = bias[cidx + 1];
            float v00 = acc[fm][fn][0] + b0, v01 = acc[fm][fn][1] + b1;
            float v10 = acc[fm][fn][2] + b0, v11 = acc[fm][fn][3] + b1;
            if (EPI == 0) {
                *(float2*)&Cout[(size_t)r0 * N + cidx] = make_float2(v00, v01);
                *(float2*)&Cout[(size_t)(r0 + 8) * N + cidx] =
                    make_float2(v10, v11);
            } else {
                const int reg = cidx >> 10;
                const int idx = cidx & 1023;
                const int h = idx >> 6, d = idx & 63;
#pragma unroll
                for (int rr = 0; rr < 2; ++rr) {
                    const int m = r0 + rr * 8;
                    const int bb = m >> 11, t = m & 2047;
                    float va = rr ? v10 : v00;
                    float vb = rr ? v11 : v01;
                    const size_t off =
                        ((size_t)(bb * NH + h) * TT + t) * HD + d;
                    if (reg == 0) {
                        va *= 0.125f; vb *= 0.125f;
                        __half ha = __float2half_rn(va);
                        __half hb = __float2half_rn(vb);
                        *(__half2*)&Qhi[off] = __halves2half2(ha, hb);
                        *(__half2*)&Qlo[off] = __floats2half2_rn(
                            va - __half2float(ha), vb - __half2float(hb));
                    } else if (reg == 1) {
                        *(__half2*)&K16[off] = __floats2half2_rn(va, vb);
                    } else {
                        *(__half2*)&Vh[off] = __floats2half2_rn(va, vb);
                    }
                }
            }
        }
    }
}

// ---------------------------------------------------------------------------
// Flash attention, all-fp16 mma.sync.
// CTA: 128 queries x one (b,h). 8 warps; warp = 16 q rows x full 64-key tile.
// S = (Qhi+Qlo) K16^T (2 fp16 terms, Q exact); P,V fp16 for PV.
// smem: Qhi(16K)|Qlo(16K)| 2 stages x [K16 8K | V 8K] = 64K (+pad).
// Epilogue: y fp16 single plane [M][C].
// ---------------------------------------------------------------------------
#define AQHI 0
#define AQLO 16384
#define ASTG 32768
#define STGB 16384
#define ATT_SMEM (ASTG + 2 * STGB + 1024)

__global__ __launch_bounds__(256, 2) void attn_mma_kernel(
    const __half* __restrict__ Qhi, const __half* __restrict__ Qlo,
    const __half* __restrict__ K16, const __half* __restrict__ V,
    __half* __restrict__ Y16)
{
    extern __shared__ char dsm[];
    const uint32_t dbase = smem_u32(dsm);
    const uint32_t sb = (dbase + 1023) & ~1023u;

    const int tid = threadIdx.x;
    const int lane = tid & 31;
    const int w = tid >> 5;
    const int qt = (int)gridDim.x - 1 - (int)blockIdx.x;
    const int bh = blockIdx.y;

    const size_t headbase = (size_t)bh * TT * HD;
    const __half* Qhig = Qhi + headbase + (size_t)qt * 128 * HD;
    const __half* Qlog = Qlo + headbase + (size_t)qt * 128 * HD;
    const __half* Kg = K16 + headbase;
    const __half* Vg = V + headbase;

    // prologue: Q (hi+lo) + tile 0
#pragma unroll
    for (int i = 0; i < 4; ++i) {
        const int c = tid + i * 256;  // 1024 x 16B chunks per 16KB matrix
        const int row = c >> 3, cu = c & 7;
        const uint32_t so = swz(row * 128 + cu * 16);
        cp16(sb + AQHI + so, Qhig + row * HD + cu * 8);
        cp16(sb + AQLO + so, Qlog + row * HD + cu * 8);
    }
    {
        const uint32_t stg = sb + ASTG;
#pragma unroll
        for (int i = 0; i < 2; ++i) {
            const int c = tid + i * 256;  // 512 chunks per 8KB matrix
            const int row = c >> 3, cu = c & 7;
            const uint32_t so = swz(row * 128 + cu * 16);
            const size_t go = (size_t)row * HD + cu * 8;
            cp16(stg + so, Kg + go);
            cp16(stg + 8192 + so, Vg + go);
        }
    }
    cp_commit();

    float oc[8][4];
#pragma unroll
    for (int f = 0; f < 8; ++f)
#pragma unroll
        for (int r = 0; r < 4; ++r) oc[f][r] = 0.f;
    float m0 = -1e30f, m1 = -1e30f, l0 = 0.f, l1 = 0.f;

    const uint32_t aBase = (uint32_t)((w * 16 + (lane & 15)) * 128 +
                                      ((lane >> 4) << 4));
    const uint32_t bRow = ((lane >> 4) << 3) + (lane & 7);
    const uint32_t bColB = ((lane >> 3) & 1) << 4;
    const uint32_t vRow = (((lane >> 3) & 1) << 3) + (lane & 7);
    const uint32_t vColB = (lane >> 4) << 4;

    const int nkt = 2 * qt + 2;
    for (int kt = 0; kt < nkt; ++kt) {
        if (kt + 1 < nkt) {  // prefetch next K/V tile
            const uint32_t stg = sb + ASTG + ((kt + 1) & 1) * STGB;
            const size_t kbase = (size_t)(kt + 1) * 64 * HD;
#pragma unroll
            for (int i = 0; i < 2; ++i) {
                const int c = tid + i * 256;
                const int row = c >> 3, cu = c & 7;
                const uint32_t so = swz(row * 128 + cu * 16);
                const size_t go = kbase + (size_t)row * HD + cu * 8;
                cp16(stg + so, Kg + go);
                cp16(stg + 8192 + so, Vg + go);
            }
        }
        cp_commit();
        cp_wait<1>();
        __syncthreads();

        const uint32_t stg = sb + ASTG + (kt & 1) * STGB;

        // ---- S = (Qhi + Qlo) K16^T ----
        float sc[8][4];
#pragma unroll
        for (int f = 0; f < 8; ++f)
#pragma unroll
            for (int r = 0; r < 4; ++r) sc[f][r] = 0.f;

#pragma unroll
        for (int kk = 0; kk < 4; ++kk) {
            uint32_t bk[4][4];
#pragma unroll
            for (int g = 0; g < 4; ++g)
                ldsm4(bk[g][0], bk[g][1], bk[g][2], bk[g][3],
                      stg + swz((g * 16 + bRow) * 128 + kk * 32 + bColB));
            uint32_t aq[4];
            ldsm4(aq[0], aq[1], aq[2], aq[3], sb + AQHI + swz(aBase + kk * 32));
#pragma unroll
            for (int f = 0; f < 8; ++f)
                mma_f16(sc[f], aq, &bk[f >> 1][(f & 1) * 2]);
            ldsm4(aq[0], aq[1], aq[2], aq[3], sb + AQLO + swz(aBase + kk * 32));
#pragma unroll
            for (int f = 0; f < 8; ++f)
                mma_f16(sc[f], aq, &bk[f >> 1][(f & 1) * 2]);
        }

        // ---- causal mask ----
        if (kt >= 2 * qt) {
            const int rq = qt * 128 + w * 16 + (lane >> 2);
#pragma unroll
            for (int f = 0; f < 8; ++f) {
                const int cg = kt * 64 + f * 8 + 2 * (lane & 3);
                if (cg > rq) sc[f][0] = -1e30f;
                if (cg + 1 > rq) sc[f][1] = -1e30f;
                if (cg > rq + 8) sc[f][2] = -1e30f;
                if (cg + 1 > rq + 8) sc[f][3] = -1e30f;
            }
        }

        // ---- online softmax (rows r, r+8; 4-lane shuffles) ----
        float mx0 = -1e30f, mx1 = -1e30f;
#pragma unroll
        for (int f = 0; f < 8; ++f) {
            mx0 = fmaxf(mx0, fmaxf(sc[f][0], sc[f][1]));
            mx1 = fmaxf(mx1, fmaxf(sc[f][2], sc[f][3]));
        }
        mx0 = fmaxf(mx0, __shfl_xor_sync(0xffffffffu, mx0, 1));
        mx0 = fmaxf(mx0, __shfl_xor_sync(0xffffffffu, mx0, 2));
        mx1 = fmaxf(mx1, __shfl_xor_sync(0xffffffffu, mx1, 1));
        mx1 = fmaxf(mx1, __shfl_xor_sync(0xffffffffu, mx1, 2));
        const float mn0 = fmaxf(m0, mx0), mn1 = fmaxf(m1, mx1);
        const float al0 = __expf(m0 - mn0), al1 = __expf(m1 - mn1);
        float rs0 = 0.f, rs1 = 0.f;
#pragma unroll
        for (int f = 0; f < 8; ++f) {
            sc[f][0] = __expf(sc[f][0] - mn0);
            sc[f][1] = __expf(sc[f][1] - mn0);
            sc[f][2] = __expf(sc[f][2] - mn1);
            sc[f][3] = __expf(sc[f][3] - mn1);
            rs0 += sc[f][0] + sc[f][1];
            rs1 += sc[f][2] + sc[f][3];
        }
        rs0 += __shfl_xor_sync(0xffffffffu, rs0, 1);
        rs0 += __shfl_xor_sync(0xffffffffu, rs0, 2);
        rs1 += __shfl_xor_sync(0xffffffffu, rs1, 1);
        rs1 += __shfl_xor_sync(0xffffffffu, rs1, 2);
        m0 = mn0; m1 = mn1;
        l0 = l0 * al0 + rs0;
        l1 = l1 * al1 + rs1;
#pragma unroll
        for (int f = 0; f < 8; ++f) {
            oc[f][0] *= al0; oc[f][1] *= al0;
            oc[f][2] *= al1; oc[f][3] *= al1;
        }

        // ---- P (fp16, registers) ----
        uint32_t pa[4][4];
#pragma unroll
        for (int j = 0; j < 4; ++j) {
            pa[j][0] = packh2(sc[2 * j][0], sc[2 * j][1]);
            pa[j][1] = packh2(sc[2 * j][2], sc[2 * j][3]);
            pa[j][2] = packh2(sc[2 * j + 1][0], sc[2 * j + 1][1]);
            pa[j][3] = packh2(sc[2 * j + 1][2], sc[2 * j + 1][3]);
        }

        // ---- O += P V ----
#pragma unroll
        for (int kb = 0; kb < 4; ++kb) {
            uint32_t bv[4][4];
#pragma unroll
            for (int g = 0; g < 4; ++g)
                ldsm4t(bv[g][0], bv[g][1], bv[g][2], bv[g][3],
                       stg + 8192 +
                           swz((kb * 16 + vRow) * 128 + g * 32 + vColB));
#pragma unroll
            for (int f = 0; f < 8; ++f)
                mma_f16(oc[f], pa[kb], &bv[f >> 1][(f & 1) * 2]);
        }
        __syncthreads();
    }

    // ---- epilogue: write y fp16 single plane [M][C] ----
    const float inv0 = 1.f / l0, inv1 = 1.f / l1;
    const int b = bh >> 4, h = bh & 15;
    const int t0 = qt * 128 + w * 16 + (lane >> 2);
    const size_t mr0 = (size_t)(b * TT + t0) * CC;
    const size_t mr1 = mr0 + (size_t)8 * CC;
#pragma unroll
    for (int f = 0; f < 8; ++f) {
        const int n = h * HD + f * 8 + 2 * (lane & 3);
#pragma unroll
        for (int rr = 0; rr < 2; ++rr) {
            const size_t base = rr ? mr1 : mr0;
            const float va = (rr ? oc[f][2] * inv1 : oc[f][0] * inv0);
            const float vb = (rr ? oc[f][3] * inv1 : oc[f][1] * inv0);
            *(__half2*)&Y16[base + n] = __floats2half2_rn(va, vb);
        }
    }
}

// ---------------------------------------------------------------------------
// launch
// ---------------------------------------------------------------------------
extern "C" void kernel_launch(void* const* d_in, const int* in_sizes, int n_in,
                              void* d_out, int out_size)
{
    (void)in_sizes; (void)n_in; (void)out_size;
    const float* x      = (const float*)d_in[0];
    const float* W_attn = (const float*)d_in[1];
    const float* b_attn = (const float*)d_in[2];
    const float* W_proj = (const float*)d_in[3];
    const float* b_proj = (const float*)d_in[4];
    float* out = (float*)d_out;

    __half *x16, *wa2, *wp2, *y16, *qhi, *qlo, *k16, *vh;
    cudaGetSymbolAddress((void**)&x16, g_x16);
    cudaGetSymbolAddress((void**)&wa2, g_wa2);
    cudaGetSymbolAddress((void**)&wp2, g_wp2);
    cudaGetSymbolAddress((void**)&y16, g_y16);
    cudaGetSymbolAddress((void**)&qhi, g_qhi);
    cudaGetSymbolAddress((void**)&qlo, g_qlo);
    cudaGetSymbolAddress((void**)&k16, g_k16);
    cudaGetSymbolAddress((void**)&vh, g_v);

    cudaFuncSetAttribute(gemm_f16_kernel<1>,
                         cudaFuncAttributeMaxDynamicSharedMemorySize,
                         NSTAGE * STAGE);
    cudaFuncSetAttribute(gemm_f16_kernel<0>,
                         cudaFuncAttributeMaxDynamicSharedMemorySize,
                         NSTAGE * STAGE);
    cudaFuncSetAttribute(attn_mma_kernel,
                         cudaFuncAttributeMaxDynamicSharedMemorySize, ATT_SMEM);

    // 0) converts
    {
        const int n4 = MTOT * CC / 4;
        convert_f16_kernel<<<(n4 + 255) / 256, 256>>>(x, x16, n4);
        dim3 tb(32, 8);
        dim3 gb(3 * CC / 32, CC / 32);
        transpose_split2_f16_kernel<<<gb, tb>>>(W_attn, wa2, CC, 3 * CC);
        dim3 gp(CC / 32, CC / 32);
        transpose_split2_f16_kernel<<<gp, tb>>>(W_proj, wp2, CC, CC);
    }
    // 1) QKV GEMM -> Q fp16 hi/lo + K fp16 + V fp16, head-major
    {
        dim3 grid(3 * CC / 128, MTOT / 128);  // (24, 32)
        gemm_f16_kernel<1><<<grid, 256, NSTAGE * STAGE>>>(
            x16, wa2, b_attn, nullptr, qhi, qlo, k16, vh, 3 * CC);
    }
    // 2) attention -> y fp16 single plane
    {
        dim3 grid(TT / 128, BB * NH);
        attn_mma_kernel<<<grid, 256, ATT_SMEM>>>(qhi, qlo, k16, vh, y16);
    }
    // 3) out = y @ W_proj + b_proj (fp16 2-term, K-folded A)
    {
        dim3 grid(CC / 128, MTOT / 128);  // (8, 32)
        gemm_f16_kernel<0><<<grid, 256, NSTAGE * STAGE>>>(
            y16, wp2, b_proj, out, nullptr, nullptr, nullptr, nullptr, CC);
    }
}

// round 10
// speedup vs baseline: 1.6180x; 1.0593x over previous
#include <cuda_runtime.h>
#include <cuda_bf16.h>
#include <cuda_fp16.h>
#include <cstdint>
#include <cstddef>

// ---------------------------------------------------------------------------
// MultiHeadAttention: x@W_attn+b -> causal MHA -> @W_proj+b
// B=2, T=2048, C=1024, H=16, D=64.
// Round 10: all-fp16 mma.sync. GEMM1: x16 @ [Wh|Wl] 2-term (V cols 1-term);
// attention: Q16 K16^T single-term + fp16 PV; GEMM2: y16 @ [Wh|Wl] 2-term.
// ---------------------------------------------------------------------------

#define BB 2
#define TT 2048
#define CC 1024
#define NH 16
#define HD 64
#define MTOT (BB * TT)  // 4096
#define K2 (2 * CC)     // 2048

// ------------------------------ scratch ------------------------------------
__device__ __half g_x16[MTOT * CC];        // x fp16 (single plane)
__device__ __half g_wa2[3 * CC * K2];      // W_attn^T [3C][2K]=[Wh|Wl]
__device__ __half g_wp2[CC * K2];          // W_proj^T [C][2K]=[Wh|Wl]
__device__ __half g_y16[MTOT * CC];        // y fp16 (single plane)
__device__ __half g_q16[BB * NH * TT * HD];  // Q/8 fp16, head-major
__device__ __half g_k16[BB * NH * TT * HD];  // K fp16
__device__ __half g_v[BB * NH * TT * HD];    // V fp16

// ------------------------------ helpers ------------------------------------
__device__ __forceinline__ uint32_t smem_u32(const void* p) {
    uint32_t a;
    asm("{ .reg .u64 t; cvta.to.shared.u64 t, %1; cvt.u32.u64 %0, t; }"
        : "=r"(a) : "l"(p));
    return a;
}
__device__ __forceinline__ uint32_t swz(uint32_t x) {  // SW128 (128B rows)
    return x ^ ((x >> 3) & 0x70);
}
__device__ __forceinline__ void cp16(uint32_t dst, const void* src) {
    asm volatile("cp.async.cg.shared.global [%0], [%1], 16;"
                 :: "r"(dst), "l"(src));
}
__device__ __forceinline__ void cp_commit() {
    asm volatile("cp.async.commit_group;");
}
template <int N>
__device__ __forceinline__ void cp_wait() {
    asm volatile("cp.async.wait_group %0;" :: "n"(N));
}
__device__ __forceinline__ void ldsm4(uint32_t& r0, uint32_t& r1, uint32_t& r2,
                                      uint32_t& r3, uint32_t addr) {
    asm volatile("ldmatrix.sync.aligned.m8n8.x4.shared.b16 {%0,%1,%2,%3}, [%4];"
                 : "=r"(r0), "=r"(r1), "=r"(r2), "=r"(r3) : "r"(addr));
}
__device__ __forceinline__ void ldsm4t(uint32_t& r0, uint32_t& r1, uint32_t& r2,
                                       uint32_t& r3, uint32_t addr) {
    asm volatile(
        "ldmatrix.sync.aligned.m8n8.x4.trans.shared.b16 {%0,%1,%2,%3}, [%4];"
        : "=r"(r0), "=r"(r1), "=r"(r2), "=r"(r3) : "r"(addr));
}
__device__ __forceinline__ void mma_f16(float* c, const uint32_t* a,
                                        const uint32_t* b) {
    asm volatile(
        "mma.sync.aligned.m16n8k16.row.col.f32.f16.f16.f32 "
        "{%0,%1,%2,%3}, {%4,%5,%6,%7}, {%8,%9}, {%0,%1,%2,%3};"
        : "+f"(c[0]), "+f"(c[1]), "+f"(c[2]), "+f"(c[3])
        : "r"(a[0]), "r"(a[1]), "r"(a[2]), "r"(a[3]), "r"(b[0]), "r"(b[1]));
}
__device__ __forceinline__ uint32_t packh2(float a, float b) {
    __half2 h = __floats2half2_rn(a, b);
    return *reinterpret_cast<uint32_t*>(&h);
}

// ---------------------------------------------------------------------------
// convert_f16: X fp32 -> fp16 (single plane)
// ---------------------------------------------------------------------------
__global__ __launch_bounds__(256) void convert_f16_kernel(
    const float* __restrict__ X, __half* __restrict__ O, int n4)
{
    int i = blockIdx.x * blockDim.x + threadIdx.x;
    if (i >= n4) return;
    float4 v = ((const float4*)X)[i];
    ((__half2*)O)[i * 2 + 0] = __floats2half2_rn(v.x, v.y);
    ((__half2*)O)[i * 2 + 1] = __floats2half2_rn(v.z, v.w);
}

// ---------------------------------------------------------------------------
// transpose_split2_f16: W [K][N] fp32 -> B2 [N][2K] fp16 = [Wh | Wl]
// ---------------------------------------------------------------------------
__global__ __launch_bounds__(256) void transpose_split2_f16_kernel(
    const float* __restrict__ W, __half* __restrict__ B2, int K, int N)
{
    __shared__ float t[32][33];
    const int n0 = blockIdx.x * 32, k0 = blockIdx.y * 32;
    const int tx = threadIdx.x, ty = threadIdx.y;
#pragma unroll
    for (int i = 0; i < 32; i += 8)
        t[ty + i][tx] = W[(size_t)(k0 + ty + i) * N + n0 + tx];
    __syncthreads();
#pragma unroll
    for (int i = 0; i < 32; i += 8) {
        const int n = n0 + ty + i, k = k0 + tx;
        const float v = t[tx][ty + i];
        const __half h = __float2half_rn(v);
        __half* row = B2 + (size_t)n * (2 * K);
        row[k] = h;
        row[K + k] = __float2half_rn(v - __half2float(h));
    }
}

// ---------------------------------------------------------------------------
// fp16 mma.sync GEMM: C = A16 @ B2^T (+bias), B2=[Wh|Wl], A folded (k & 1023).
// CTA 128x128, BK=64, 3 stages, 2 CTA/SM, 8 warps (2x4), warp 64x32.
// EPI=0: fp32 out + bias (NCH=32).
// EPI=1: QKV epilogue; V column tiles (n0>=2048) use NCH=16 (single term).
//        Q pre-scaled 0.125, single fp16.
// ---------------------------------------------------------------------------
#define BKB 128
#define TILE_A 16384
#define STAGE 32768
#define NSTAGE 3

template <int EPI>
__global__ __launch_bounds__(256, 2) void gemm_f16_kernel(
    const __half* __restrict__ A, const __half* __restrict__ B,
    const float* __restrict__ bias, float* __restrict__ Cout,
    __half* __restrict__ Q16, __half* __restrict__ K16,
    __half* __restrict__ Vh, int N)
{
    extern __shared__ char dsm[];
    const uint32_t sbase = smem_u32(dsm);

    const int tid = threadIdx.x;
    const int lane = tid & 31;
    const int warp = tid >> 5;
    const int wm = warp >> 2;
    const int wn = warp & 3;
    const int n0 = blockIdx.x * 128;
    const int m0 = blockIdx.y * 128;

    const int NCH = (EPI == 1 && n0 >= 2048) ? 16 : 32;

    const int ldrow = tid >> 1;
    const int cgrp = (tid & 1) * 4;
    const __half* aRow = A + (size_t)(m0 + ldrow) * CC + cgrp * 8;
    const __half* bRow = B + (size_t)(n0 + ldrow) * K2 + cgrp * 8;
    uint32_t dstOff[4];
#pragma unroll
    for (int j = 0; j < 4; ++j)
        dstOff[j] = swz(ldrow * BKB + (cgrp + j) * 16);

#pragma unroll
    for (int c = 0; c < NSTAGE - 1; ++c) {
        const uint32_t sA = sbase + c * STAGE;
        const uint32_t sB = sA + TILE_A;
#pragma unroll
        for (int j = 0; j < 4; ++j) {
            cp16(sA + dstOff[j], aRow + (c & 15) * 64 + j * 8);
            cp16(sB + dstOff[j], bRow + c * 64 + j * 8);
        }
        cp_commit();
    }

    float acc[4][4][4];
#pragma unroll
    for (int i = 0; i < 4; ++i)
#pragma unroll
        for (int j = 0; j < 4; ++j)
#pragma unroll
            for (int r = 0; r < 4; ++r) acc[i][j][r] = 0.f;

    const int arow = wm * 64 + (lane & 15);
    const uint32_t acolbase = (lane >> 4) << 4;
    const int brow = wn * 32 + ((lane >> 4) << 3) + (lane & 7);
    const uint32_t bcolbase = ((lane >> 3) & 1) << 4;

    for (int c = 0; c < NCH; ++c) {
        cp_wait<NSTAGE - 2>();
        __syncthreads();

        if (c + NSTAGE - 1 < NCH) {
            const int cc = c + NSTAGE - 1;
            const uint32_t sA = sbase + (cc % NSTAGE) * STAGE;
            const uint32_t sB = sA + TILE_A;
#pragma unroll
            for (int j = 0; j < 4; ++j) {
                cp16(sA + dstOff[j], aRow + (cc & 15) * 64 + j * 8);
                cp16(sB + dstOff[j], bRow + (size_t)cc * 64 + j * 8);
            }
        }
        cp_commit();

        const uint32_t sA = sbase + (c % NSTAGE) * STAGE;
        const uint32_t sB = sA + TILE_A;

#pragma unroll
        for (int kk = 0; kk < 4; ++kk) {
            uint32_t af[4][4], bf[2][4];
#pragma unroll
            for (int fm = 0; fm < 4; ++fm) {
                const int r = arow + fm * 16;
                ldsm4(af[fm][0], af[fm][1], af[fm][2], af[fm][3],
                      sA + swz((uint32_t)r * BKB + kk * 32 + acolbase));
            }
#pragma unroll
            for (int fn2 = 0; fn2 < 2; ++fn2) {
                const int r = brow + fn2 * 16;
                ldsm4(bf[fn2][0], bf[fn2][1], bf[fn2][2], bf[fn2][3],
                      sB + swz((uint32_t)r * BKB + kk * 32 + bcolbase));
            }
#pragma unroll
            for (int fm = 0; fm < 4; ++fm)
#pragma unroll
                for (int fn = 0; fn < 4; ++fn)
                    mma_f16(acc[fm][fn], af[fm], &bf[fn >> 1][(fn & 1) * 2]);
        }
        __syncthreads();
    }

    // epilogue
#pragma unroll
    for (int fm = 0; fm < 4; ++fm) {
        const int r0 = m0 + wm * 64 + fm * 16 + (lane >> 2);
#pragma unroll
        for (int fn = 0; fn < 4; ++fn) {
            const int cidx = n0 + wn * 32 + fn * 8 + (lane & 3) * 2;
            const float b0 = bias[cidx], b1 = bias[cidx + 1];
            float v00 = acc[fm][fn][0] + b0, v01 = acc[fm][fn][1] + b1;
            float v10 = acc[fm][fn][2] + b0, v11 = acc[fm][fn][3] + b1;
            if (EPI == 0) {
                *(float2*)&Cout[(size_t)r0 * N + cidx] = make_float2(v00, v01);
                *(float2*)&Cout[(size_t)(r0 + 8) * N + cidx] =
                    make_float2(v10, v11);
            } else {
                const int reg = cidx >> 10;
                const int idx = cidx & 1023;
                const int h = idx >> 6, d = idx & 63;
#pragma unroll
                for (int rr = 0; rr < 2; ++rr) {
                    const int m = r0 + rr * 8;
                    const int bb = m >> 11, t = m & 2047;
                    float va = rr ? v10 : v00;
                    float vb = rr ? v11 : v01;
                    const size_t off =
                        ((size_t)(bb * NH + h) * TT + t) * HD + d;
                    if (reg == 0) {
                        *(__half2*)&Q16[off] =
                            __floats2half2_rn(va * 0.125f, vb * 0.125f);
                    } else if (reg == 1) {
                        *(__half2*)&K16[off] = __floats2half2_rn(va, vb);
                    } else {
                        *(__half2*)&Vh[off] = __floats2half2_rn(va, vb);
                    }
                }
            }
        }
    }
}

// ---------------------------------------------------------------------------
// Flash attention, all-fp16 mma.sync, single-term QK.
// CTA: 128 queries x one (b,h). 8 warps; warp = 16 q rows x full 64-key tile.
// smem: Q(16K) | 2 stages x [K16 8K | V 8K] = 48K (+pad).
// Epilogue: y fp16 single plane [M][C].
// ---------------------------------------------------------------------------
#define AQ16 0
#define ASTG 16384
#define STGB 16384
#define ATT_SMEM (ASTG + 2 * STGB + 1024)

__global__ __launch_bounds__(256, 2) void attn_mma_kernel(
    const __half* __restrict__ Q16, const __half* __restrict__ K16,
    const __half* __restrict__ V, __half* __restrict__ Y16)
{
    extern __shared__ char dsm[];
    const uint32_t dbase = smem_u32(dsm);
    const uint32_t sb = (dbase + 1023) & ~1023u;

    const int tid = threadIdx.x;
    const int lane = tid & 31;
    const int w = tid >> 5;
    const int qt = (int)gridDim.x - 1 - (int)blockIdx.x;
    const int bh = blockIdx.y;

    const size_t headbase = (size_t)bh * TT * HD;
    const __half* Qg = Q16 + headbase + (size_t)qt * 128 * HD;
    const __half* Kg = K16 + headbase;
    const __half* Vg = V + headbase;

    // prologue: Q + tile 0
#pragma unroll
    for (int i = 0; i < 4; ++i) {
        const int c = tid + i * 256;  // 1024 x 16B chunks for 16KB Q
        const int row = c >> 3, cu = c & 7;
        cp16(sb + AQ16 + swz(row * 128 + cu * 16), Qg + row * HD + cu * 8);
    }
    {
        const uint32_t stg = sb + ASTG;
#pragma unroll
        for (int i = 0; i < 2; ++i) {
            const int c = tid + i * 256;  // 512 chunks per 8KB matrix
            const int row = c >> 3, cu = c & 7;
            const uint32_t so = swz(row * 128 + cu * 16);
            const size_t go = (size_t)row * HD + cu * 8;
            cp16(stg + so, Kg + go);
            cp16(stg + 8192 + so, Vg + go);
        }
    }
    cp_commit();

    float oc[8][4];
#pragma unroll
    for (int f = 0; f < 8; ++f)
#pragma unroll
        for (int r = 0; r < 4; ++r) oc[f][r] = 0.f;
    float m0 = -1e30f, m1 = -1e30f, l0 = 0.f, l1 = 0.f;

    const uint32_t aBase = (uint32_t)((w * 16 + (lane & 15)) * 128 +
                                      ((lane >> 4) << 4));
    const uint32_t bRow = ((lane >> 4) << 3) + (lane & 7);
    const uint32_t bColB = ((lane >> 3) & 1) << 4;
    const uint32_t vRow = (((lane >> 3) & 1) << 3) + (lane & 7);
    const uint32_t vColB = (lane >> 4) << 4;

    const int nkt = 2 * qt + 2;
    for (int kt = 0; kt < nkt; ++kt) {
        if (kt + 1 < nkt) {  // prefetch next K/V tile
            const uint32_t stg = sb + ASTG + ((kt + 1) & 1) * STGB;
            const size_t kbase = (size_t)(kt + 1) * 64 * HD;
#pragma unroll
            for (int i = 0; i < 2; ++i) {
                const int c = tid + i * 256;
                const int row = c >> 3, cu = c & 7;
                const uint32_t so = swz(row * 128 + cu * 16);
                const size_t go = kbase + (size_t)row * HD + cu * 8;
                cp16(stg + so, Kg + go);
                cp16(stg + 8192 + so, Vg + go);
            }
        }
        cp_commit();
        cp_wait<1>();
        __syncthreads();

        const uint32_t stg = sb + ASTG + (kt & 1) * STGB;

        // ---- S = Q16 K16^T (single term) ----
        float sc[8][4];
#pragma unroll
        for (int f = 0; f < 8; ++f)
#pragma unroll
            for (int r = 0; r < 4; ++r) sc[f][r] = 0.f;

#pragma unroll
        for (int kk = 0; kk < 4; ++kk) {
            uint32_t bk[4][4];
#pragma unroll
            for (int g = 0; g < 4; ++g)
                ldsm4(bk[g][0], bk[g][1], bk[g][2], bk[g][3],
                      stg + swz((g * 16 + bRow) * 128 + kk * 32 + bColB));
            uint32_t aq[4];
            ldsm4(aq[0], aq[1], aq[2], aq[3], sb + AQ16 + swz(aBase + kk * 32));
#pragma unroll
            for (int f = 0; f < 8; ++f)
                mma_f16(sc[f], aq, &bk[f >> 1][(f & 1) * 2]);
        }

        // ---- causal mask ----
        if (kt >= 2 * qt) {
            const int rq = qt * 128 + w * 16 + (lane >> 2);
#pragma unroll
            for (int f = 0; f < 8; ++f) {
                const int cg = kt * 64 + f * 8 + 2 * (lane & 3);
                if (cg > rq) sc[f][0] = -1e30f;
                if (cg + 1 > rq) sc[f][1] = -1e30f;
                if (cg > rq + 8) sc[f][2] = -1e30f;
                if (cg + 1 > rq + 8) sc[f][3] = -1e30f;
            }
        }

        // ---- online softmax (rows r, r+8; 4-lane shuffles) ----
        float mx0 = -1e30f, mx1 = -1e30f;
#pragma unroll
        for (int f = 0; f < 8; ++f) {
            mx0 = fmaxf(mx0, fmaxf(sc[f][0], sc[f][1]));
            mx1 = fmaxf(mx1, fmaxf(sc[f][2], sc[f][3]));
        }
        mx0 = fmaxf(mx0, __shfl_xor_sync(0xffffffffu, mx0, 1));
        mx0 = fmaxf(mx0, __shfl_xor_sync(0xffffffffu, mx0, 2));
        mx1 = fmaxf(mx1, __shfl_xor_sync(0xffffffffu, mx1, 1));
        mx1 = fmaxf(mx1, __shfl_xor_sync(0xffffffffu, mx1, 2));
        const float mn0 = fmaxf(m0, mx0), mn1 = fmaxf(m1, mx1);
        const float al0 = __expf(m0 - mn0), al1 = __expf(m1 - mn1);
        float rs0 = 0.f, rs1 = 0.f;
#pragma unroll
        for (int f = 0; f < 8; ++f) {
            sc[f][0] = __expf(sc[f][0] - mn0);
            sc[f][1] = __expf(sc[f][1] - mn0);
            sc[f][2] = __expf(sc[f][2] - mn1);
            sc[f][3] = __expf(sc[f][3] - mn1);
            rs0 += sc[f][0] + sc[f][1];
            rs1 += sc[f][2] + sc[f][3];
        }
        rs0 += __shfl_xor_sync(0xffffffffu, rs0, 1);
        rs0 += __shfl_xor_sync(0xffffffffu, rs0, 2);
        rs1 += __shfl_xor_sync(0xffffffffu, rs1, 1);
        rs1 += __shfl_xor_sync(0xffffffffu, rs1, 2);
        m0 = mn0; m1 = mn1;
        l0 = l0 * al0 + rs0;
        l1 = l1 * al1 + rs1;
#pragma unroll
        for (int f = 0; f < 8; ++f) {
            oc[f][0] *= al0; oc[f][1] *= al0;
            oc[f][2] *= al1; oc[f][3] *= al1;
        }

        // ---- P (fp16, registers) ----
        uint32_t pa[4][4];
#pragma unroll
        for (int j = 0; j < 4; ++j) {
            pa[j][0] = packh2(sc[2 * j][0], sc[2 * j][1]);
            pa[j][1] = packh2(sc[2 * j][2], sc[2 * j][3]);
            pa[j][2] = packh2(sc[2 * j + 1][0], sc[2 * j + 1][1]);
            pa[j][3] = packh2(sc[2 * j + 1][2], sc[2 * j + 1][3]);
        }

        // ---- O += P V ----
#pragma unroll
        for (int kb = 0; kb < 4; ++kb) {
            uint32_t bv[4][4];
#pragma unroll
            for (int g = 0; g < 4; ++g)
                ldsm4t(bv[g][0], bv[g][1], bv[g][2], bv[g][3],
                       stg + 8192 +
                           swz((kb * 16 + vRow) * 128 + g * 32 + vColB));
#pragma unroll
            for (int f = 0; f < 8; ++f)
                mma_f16(oc[f], pa[kb], &bv[f >> 1][(f & 1) * 2]);
        }
        __syncthreads();
    }

    // ---- epilogue: write y fp16 single plane [M][C] ----
    const float inv0 = 1.f / l0, inv1 = 1.f / l1;
    const int b = bh >> 4, h = bh & 15;
    const int t0 = qt * 128 + w * 16 + (lane >> 2);
    const size_t mr0 = (size_t)(b * TT + t0) * CC;
    const size_t mr1 = mr0 + (size_t)8 * CC;
#pragma unroll
    for (int f = 0; f < 8; ++f) {
        const int n = h * HD + f * 8 + 2 * (lane & 3);
#pragma unroll
        for (int rr = 0; rr < 2; ++rr) {
            const size_t base = rr ? mr1 : mr0;
            const float va = (rr ? oc[f][2] * inv1 : oc[f][0] * inv0);
            const float vb = (rr ? oc[f][3] * inv1 : oc[f][1] * inv0);
            *(__half2*)&Y16[base + n] = __floats2half2_rn(va, vb);
        }
    }
}

// ---------------------------------------------------------------------------
// launch
// ---------------------------------------------------------------------------
extern "C" void kernel_launch(void* const* d_in, const int* in_sizes, int n_in,
                              void* d_out, int out_size)
{
    (void)in_sizes; (void)n_in; (void)out_size;
    const float* x      = (const float*)d_in[0];
    const float* W_attn = (const float*)d_in[1];
    const float* b_attn = (const float*)d_in[2];
    const float* W_proj = (const float*)d_in[3];
    const float* b_proj = (const float*)d_in[4];
    float* out = (float*)d_out;

    __half *x16, *wa2, *wp2, *y16, *q16, *k16, *vh;
    cudaGetSymbolAddress((void**)&x16, g_x16);
    cudaGetSymbolAddress((void**)&wa2, g_wa2);
    cudaGetSymbolAddress((void**)&wp2, g_wp2);
    cudaGetSymbolAddress((void**)&y16, g_y16);
    cudaGetSymbolAddress((void**)&q16, g_q16);
    cudaGetSymbolAddress((void**)&k16, g_k16);
    cudaGetSymbolAddress((void**)&vh, g_v);

    cudaFuncSetAttribute(gemm_f16_kernel<1>,
                         cudaFuncAttributeMaxDynamicSharedMemorySize,
                         NSTAGE * STAGE);
    cudaFuncSetAttribute(gemm_f16_kernel<0>,
                         cudaFuncAttributeMaxDynamicSharedMemorySize,
                         NSTAGE * STAGE);
    cudaFuncSetAttribute(attn_mma_kernel,
                         cudaFuncAttributeMaxDynamicSharedMemorySize, ATT_SMEM);

    // 0) converts
    {
        const int n4 = MTOT * CC / 4;
        convert_f16_kernel<<<(n4 + 255) / 256, 256>>>(x, x16, n4);
        dim3 tb(32, 8);
        dim3 gb(3 * CC / 32, CC / 32);
        transpose_split2_f16_kernel<<<gb, tb>>>(W_attn, wa2, CC, 3 * CC);
        dim3 gp(CC / 32, CC / 32);
        transpose_split2_f16_kernel<<<gp, tb>>>(W_proj, wp2, CC, CC);
    }
    // 1) QKV GEMM -> Q/K/V fp16, head-major
    {
        dim3 grid(3 * CC / 128, MTOT / 128);  // (24, 32)
        gemm_f16_kernel<1><<<grid, 256, NSTAGE * STAGE>>>(
            x16, wa2, b_attn, nullptr, q16, k16, vh, 3 * CC);
    }
    // 2) attention -> y fp16 single plane
    {
        dim3 grid(TT / 128, BB * NH);
        attn_mma_kernel<<<grid, 256, ATT_SMEM>>>(q16, k16, vh, y16);
    }
    // 3) out = y @ W_proj + b_proj (fp16 2-term, K-folded A)
    {
        dim3 grid(CC / 128, MTOT / 128);  // (8, 32)
        gemm_f16_kernel<0><<<grid, 256, NSTAGE * STAGE>>>(
            y16, wp2, b_proj, out, nullptr, nullptr, nullptr, CC);
    }
}

// round 11
// speedup vs baseline: 2.2734x; 1.4050x over previous
#include <cuda_runtime.h>
#include <cuda_bf16.h>
#include <cuda_fp16.h>
#include <cstdint>
#include <cstddef>

// ---------------------------------------------------------------------------
// MultiHeadAttention: x@W_attn+b -> causal MHA -> @W_proj+b
// B=2, T=2048, C=1024, H=16, D=64.
// Round 11: single-term fp16 mma.sync everywhere (K'=1024 GEMMs, 1-term QK,
// fp16 PV). All operands rounded once to fp16; fp32 accumulation throughout.
// ---------------------------------------------------------------------------

#define BB 2
#define TT 2048
#define CC 1024
#define NH 16
#define HD 64
#define MTOT (BB * TT)  // 4096

// ------------------------------ scratch ------------------------------------
__device__ __half g_x16[MTOT * CC];          // x fp16
__device__ __half g_wa[3 * CC * CC];         // W_attn^T fp16 [3C][C]
__device__ __half g_wp[CC * CC];             // W_proj^T fp16 [C][C]
__device__ __half g_y16[MTOT * CC];          // y fp16
__device__ __half g_q16[BB * NH * TT * HD];  // Q/8 fp16, head-major
__device__ __half g_k16[BB * NH * TT * HD];  // K fp16
__device__ __half g_v[BB * NH * TT * HD];    // V fp16

// ------------------------------ helpers ------------------------------------
__device__ __forceinline__ uint32_t smem_u32(const void* p) {
    uint32_t a;
    asm("{ .reg .u64 t; cvta.to.shared.u64 t, %1; cvt.u32.u64 %0, t; }"
        : "=r"(a) : "l"(p));
    return a;
}
__device__ __forceinline__ uint32_t swz(uint32_t x) {  // SW128 (128B rows)
    return x ^ ((x >> 3) & 0x70);
}
__device__ __forceinline__ void cp16(uint32_t dst, const void* src) {
    asm volatile("cp.async.cg.shared.global [%0], [%1], 16;"
                 :: "r"(dst), "l"(src));
}
__device__ __forceinline__ void cp_commit() {
    asm volatile("cp.async.commit_group;");
}
template <int N>
__device__ __forceinline__ void cp_wait() {
    asm volatile("cp.async.wait_group %0;" :: "n"(N));
}
__device__ __forceinline__ void ldsm4(uint32_t& r0, uint32_t& r1, uint32_t& r2,
                                      uint32_t& r3, uint32_t addr) {
    asm volatile("ldmatrix.sync.aligned.m8n8.x4.shared.b16 {%0,%1,%2,%3}, [%4];"
                 : "=r"(r0), "=r"(r1), "=r"(r2), "=r"(r3) : "r"(addr));
}
__device__ __forceinline__ void ldsm4t(uint32_t& r0, uint32_t& r1, uint32_t& r2,
                                       uint32_t& r3, uint32_t addr) {
    asm volatile(
        "ldmatrix.sync.aligned.m8n8.x4.trans.shared.b16 {%0,%1,%2,%3}, [%4];"
        : "=r"(r0), "=r"(r1), "=r"(r2), "=r"(r3) : "r"(addr));
}
__device__ __forceinline__ void mma_f16(float* c, const uint32_t* a,
                                        const uint32_t* b) {
    asm volatile(
        "mma.sync.aligned.m16n8k16.row.col.f32.f16.f16.f32 "
        "{%0,%1,%2,%3}, {%4,%5,%6,%7}, {%8,%9}, {%0,%1,%2,%3};"
        : "+f"(c[0]), "+f"(c[1]), "+f"(c[2]), "+f"(c[3])
        : "r"(a[0]), "r"(a[1]), "r"(a[2]), "r"(a[3]), "r"(b[0]), "r"(b[1]));
}
__device__ __forceinline__ uint32_t packh2(float a, float b) {
    __half2 h = __floats2half2_rn(a, b);
    return *reinterpret_cast<uint32_t*>(&h);
}

// ---------------------------------------------------------------------------
// convert_f16: X fp32 -> fp16
// ---------------------------------------------------------------------------
__global__ __launch_bounds__(256) void convert_f16_kernel(
    const float* __restrict__ X, __half* __restrict__ O, int n4)
{
    int i = blockIdx.x * blockDim.x + threadIdx.x;
    if (i >= n4) return;
    float4 v = ((const float4*)X)[i];
    ((__half2*)O)[i * 2 + 0] = __floats2half2_rn(v.x, v.y);
    ((__half2*)O)[i * 2 + 1] = __floats2half2_rn(v.z, v.w);
}

// ---------------------------------------------------------------------------
// transpose_f16: W [K][N] fp32 -> WT [N][K] fp16
// ---------------------------------------------------------------------------
__global__ __launch_bounds__(256) void transpose_f16_kernel(
    const float* __restrict__ W, __half* __restrict__ WT, int K, int N)
{
    __shared__ float t[32][33];
    const int n0 = blockIdx.x * 32, k0 = blockIdx.y * 32;
    const int tx = threadIdx.x, ty = threadIdx.y;
#pragma unroll
    for (int i = 0; i < 32; i += 8)
        t[ty + i][tx] = W[(size_t)(k0 + ty + i) * N + n0 + tx];
    __syncthreads();
#pragma unroll
    for (int i = 0; i < 32; i += 8) {
        const int n = n0 + ty + i, k = k0 + tx;
        WT[(size_t)n * K + k] = __float2half_rn(t[tx][ty + i]);
    }
}

// ---------------------------------------------------------------------------
// fp16 mma.sync GEMM: C = A16 @ B16^T (+bias), K=1024, NCH=16.
// CTA 128x128, BK=64, 3 stages, 2 CTA/SM, 8 warps (2x4), warp 64x32.
// EPI=0: fp32 out + bias. EPI=1: QKV epilogue (Q*0.125, K, V fp16 head-major).
// ---------------------------------------------------------------------------
#define BKB 128
#define TILE_A 16384
#define STAGE 32768
#define NSTAGE 3
#define NCH (CC / 64)  // 16

template <int EPI>
__global__ __launch_bounds__(256, 2) void gemm_f16_kernel(
    const __half* __restrict__ A, const __half* __restrict__ B,
    const float* __restrict__ bias, float* __restrict__ Cout,
    __half* __restrict__ Q16, __half* __restrict__ K16,
    __half* __restrict__ Vh, int N)
{
    extern __shared__ char dsm[];
    const uint32_t sbase = smem_u32(dsm);

    const int tid = threadIdx.x;
    const int lane = tid & 31;
    const int warp = tid >> 5;
    const int wm = warp >> 2;
    const int wn = warp & 3;
    const int n0 = blockIdx.x * 128;
    const int m0 = blockIdx.y * 128;

    const int ldrow = tid >> 1;
    const int cgrp = (tid & 1) * 4;
    const __half* aRow = A + (size_t)(m0 + ldrow) * CC + cgrp * 8;
    const __half* bRow = B + (size_t)(n0 + ldrow) * CC + cgrp * 8;
    uint32_t dstOff[4];
#pragma unroll
    for (int j = 0; j < 4; ++j)
        dstOff[j] = swz(ldrow * BKB + (cgrp + j) * 16);

#pragma unroll
    for (int c = 0; c < NSTAGE - 1; ++c) {
        const uint32_t sA = sbase + c * STAGE;
        const uint32_t sB = sA + TILE_A;
#pragma unroll
        for (int j = 0; j < 4; ++j) {
            cp16(sA + dstOff[j], aRow + c * 64 + j * 8);
            cp16(sB + dstOff[j], bRow + c * 64 + j * 8);
        }
        cp_commit();
    }

    float acc[4][4][4];
#pragma unroll
    for (int i = 0; i < 4; ++i)
#pragma unroll
        for (int j = 0; j < 4; ++j)
#pragma unroll
            for (int r = 0; r < 4; ++r) acc[i][j][r] = 0.f;

    const int arow = wm * 64 + (lane & 15);
    const uint32_t acolbase = (lane >> 4) << 4;
    const int brow = wn * 32 + ((lane >> 4) << 3) + (lane & 7);
    const uint32_t bcolbase = ((lane >> 3) & 1) << 4;

    for (int c = 0; c < NCH; ++c) {
        cp_wait<NSTAGE - 2>();
        __syncthreads();

        if (c + NSTAGE - 1 < NCH) {
            const int cc = c + NSTAGE - 1;
            const uint32_t sA = sbase + (cc % NSTAGE) * STAGE;
            const uint32_t sB = sA + TILE_A;
#pragma unroll
            for (int j = 0; j < 4; ++j) {
                cp16(sA + dstOff[j], aRow + (size_t)cc * 64 + j * 8);
                cp16(sB + dstOff[j], bRow + (size_t)cc * 64 + j * 8);
            }
        }
        cp_commit();

        const uint32_t sA = sbase + (c % NSTAGE) * STAGE;
        const uint32_t sB = sA + TILE_A;

#pragma unroll
        for (int kk = 0; kk < 4; ++kk) {
            uint32_t af[4][4], bf[2][4];
#pragma unroll
            for (int fm = 0; fm < 4; ++fm) {
                const int r = arow + fm * 16;
                ldsm4(af[fm][0], af[fm][1], af[fm][2], af[fm][3],
                      sA + swz((uint32_t)r * BKB + kk * 32 + acolbase));
            }
#pragma unroll
            for (int fn2 = 0; fn2 < 2; ++fn2) {
                const int r = brow + fn2 * 16;
                ldsm4(bf[fn2][0], bf[fn2][1], bf[fn2][2], bf[fn2][3],
                      sB + swz((uint32_t)r * BKB + kk * 32 + bcolbase));
            }
#pragma unroll
            for (int fm = 0; fm < 4; ++fm)
#pragma unroll
                for (int fn = 0; fn < 4; ++fn)
                    mma_f16(acc[fm][fn], af[fm], &bf[fn >> 1][(fn & 1) * 2]);
        }
        __syncthreads();
    }

    // epilogue
#pragma unroll
    for (int fm = 0; fm < 4; ++fm) {
        const int r0 = m0 + wm * 64 + fm * 16 + (lane >> 2);
#pragma unroll
        for (int fn = 0; fn < 4; ++fn) {
            const int cidx = n0 + wn * 32 + fn * 8 + (lane & 3) * 2;
            const float b0 = bias[cidx], b1 = bias[cidx + 1];
            float v00 = acc[fm][fn][0] + b0, v01 = acc[fm][fn][1] + b1;
            float v10 = acc[fm][fn][2] + b0, v11 = acc[fm][fn][3] + b1;
            if (EPI == 0) {
                *(float2*)&Cout[(size_t)r0 * N + cidx] = make_float2(v00, v01);
                *(float2*)&Cout[(size_t)(r0 + 8) * N + cidx] =
                    make_float2(v10, v11);
            } else {
                const int reg = cidx >> 10;
                const int idx = cidx & 1023;
                const int h = idx >> 6, d = idx & 63;
#pragma unroll
                for (int rr = 0; rr < 2; ++rr) {
                    const int m = r0 + rr * 8;
                    const int bb = m >> 11, t = m & 2047;
                    float va = rr ? v10 : v00;
                    float vb = rr ? v11 : v01;
                    const size_t off =
                        ((size_t)(bb * NH + h) * TT + t) * HD + d;
                    if (reg == 0) {
                        *(__half2*)&Q16[off] =
                            __floats2half2_rn(va * 0.125f, vb * 0.125f);
                    } else if (reg == 1) {
                        *(__half2*)&K16[off] = __floats2half2_rn(va, vb);
                    } else {
                        *(__half2*)&Vh[off] = __floats2half2_rn(va, vb);
                    }
                }
            }
        }
    }
}

// ---------------------------------------------------------------------------
// Flash attention, all-fp16 mma.sync, single-term QK.
// CTA: 128 queries x one (b,h). 8 warps; warp = 16 q rows x full 64-key tile.
// smem: Q(16K) | 2 stages x [K16 8K | V 8K] = 48K (+pad).
// ---------------------------------------------------------------------------
#define AQ16 0
#define ASTG 16384
#define STGB 16384
#define ATT_SMEM (ASTG + 2 * STGB + 1024)

__global__ __launch_bounds__(256, 2) void attn_mma_kernel(
    const __half* __restrict__ Q16, const __half* __restrict__ K16,
    const __half* __restrict__ V, __half* __restrict__ Y16)
{
    extern __shared__ char dsm[];
    const uint32_t dbase = smem_u32(dsm);
    const uint32_t sb = (dbase + 1023) & ~1023u;

    const int tid = threadIdx.x;
    const int lane = tid & 31;
    const int w = tid >> 5;
    const int qt = (int)gridDim.x - 1 - (int)blockIdx.x;
    const int bh = blockIdx.y;

    const size_t headbase = (size_t)bh * TT * HD;
    const __half* Qg = Q16 + headbase + (size_t)qt * 128 * HD;
    const __half* Kg = K16 + headbase;
    const __half* Vg = V + headbase;

#pragma unroll
    for (int i = 0; i < 4; ++i) {
        const int c = tid + i * 256;
        const int row = c >> 3, cu = c & 7;
        cp16(sb + AQ16 + swz(row * 128 + cu * 16), Qg + row * HD + cu * 8);
    }
    {
        const uint32_t stg = sb + ASTG;
#pragma unroll
        for (int i = 0; i < 2; ++i) {
            const int c = tid + i * 256;
            const int row = c >> 3, cu = c & 7;
            const uint32_t so = swz(row * 128 + cu * 16);
            const size_t go = (size_t)row * HD + cu * 8;
            cp16(stg + so, Kg + go);
            cp16(stg + 8192 + so, Vg + go);
        }
    }
    cp_commit();

    float oc[8][4];
#pragma unroll
    for (int f = 0; f < 8; ++f)
#pragma unroll
        for (int r = 0; r < 4; ++r) oc[f][r] = 0.f;
    float m0 = -1e30f, m1 = -1e30f, l0 = 0.f, l1 = 0.f;

    const uint32_t aBase = (uint32_t)((w * 16 + (lane & 15)) * 128 +
                                      ((lane >> 4) << 4));
    const uint32_t bRow = ((lane >> 4) << 3) + (lane & 7);
    const uint32_t bColB = ((lane >> 3) & 1) << 4;
    const uint32_t vRow = (((lane >> 3) & 1) << 3) + (lane & 7);
    const uint32_t vColB = (lane >> 4) << 4;

    const int nkt = 2 * qt + 2;
    for (int kt = 0; kt < nkt; ++kt) {
        if (kt + 1 < nkt) {
            const uint32_t stg = sb + ASTG + ((kt + 1) & 1) * STGB;
            const size_t kbase = (size_t)(kt + 1) * 64 * HD;
#pragma unroll
            for (int i = 0; i < 2; ++i) {
                const int c = tid + i * 256;
                const int row = c >> 3, cu = c & 7;
                const uint32_t so = swz(row * 128 + cu * 16);
                const size_t go = kbase + (size_t)row * HD + cu * 8;
                cp16(stg + so, Kg + go);
                cp16(stg + 8192 + so, Vg + go);
            }
        }
        cp_commit();
        cp_wait<1>();
        __syncthreads();

        const uint32_t stg = sb + ASTG + (kt & 1) * STGB;

        float sc[8][4];
#pragma unroll
        for (int f = 0; f < 8; ++f)
#pragma unroll
            for (int r = 0; r < 4; ++r) sc[f][r] = 0.f;

#pragma unroll
        for (int kk = 0; kk < 4; ++kk) {
            uint32_t bk[4][4];
#pragma unroll
            for (int g = 0; g < 4; ++g)
                ldsm4(bk[g][0], bk[g][1], bk[g][2], bk[g][3],
                      stg + swz((g * 16 + bRow) * 128 + kk * 32 + bColB));
            uint32_t aq[4];
            ldsm4(aq[0], aq[1], aq[2], aq[3], sb + AQ16 + swz(aBase + kk * 32));
#pragma unroll
            for (int f = 0; f < 8; ++f)
                mma_f16(sc[f], aq, &bk[f >> 1][(f & 1) * 2]);
        }

        if (kt >= 2 * qt) {
            const int rq = qt * 128 + w * 16 + (lane >> 2);
#pragma unroll
            for (int f = 0; f < 8; ++f) {
                const int cg = kt * 64 + f * 8 + 2 * (lane & 3);
                if (cg > rq) sc[f][0] = -1e30f;
                if (cg + 1 > rq) sc[f][1] = -1e30f;
                if (cg > rq + 8) sc[f][2] = -1e30f;
                if (cg + 1 > rq + 8) sc[f][3] = -1e30f;
            }
        }

        float mx0 = -1e30f, mx1 = -1e30f;
#pragma unroll
        for (int f = 0; f < 8; ++f) {
            mx0 = fmaxf(mx0, fmaxf(sc[f][0], sc[f][1]));
            mx1 = fmaxf(mx1, fmaxf(sc[f][2], sc[f][3]));
        }
        mx0 = fmaxf(mx0, __shfl_xor_sync(0xffffffffu, mx0, 1));
        mx0 = fmaxf(mx0, __shfl_xor_sync(0xffffffffu, mx0, 2));
        mx1 = fmaxf(mx1, __shfl_xor_sync(0xffffffffu, mx1, 1));
        mx1 = fmaxf(mx1, __shfl_xor_sync(0xffffffffu, mx1, 2));
        const float mn0 = fmaxf(m0, mx0), mn1 = fmaxf(m1, mx1);
        const float al0 = __expf(m0 - mn0), al1 = __expf(m1 - mn1);
        float rs0 = 0.f, rs1 = 0.f;
#pragma unroll
        for (int f = 0; f < 8; ++f) {
            sc[f][0] = __expf(sc[f][0] - mn0);
            sc[f][1] = __expf(sc[f][1] - mn0);
            sc[f][2] = __expf(sc[f][2] - mn1);
            sc[f][3] = __expf(sc[f][3] - mn1);
            rs0 += sc[f][0] + sc[f][1];
            rs1 += sc[f][2] + sc[f][3];
        }
        rs0 += __shfl_xor_sync(0xffffffffu, rs0, 1);
        rs0 += __shfl_xor_sync(0xffffffffu, rs0, 2);
        rs1 += __shfl_xor_sync(0xffffffffu, rs1, 1);
        rs1 += __shfl_xor_sync(0xffffffffu, rs1, 2);
        m0 = mn0; m1 = mn1;
        l0 = l0 * al0 + rs0;
        l1 = l1 * al1 + rs1;
#pragma unroll
        for (int f = 0; f < 8; ++f) {
            oc[f][0] *= al0; oc[f][1] *= al0;
            oc[f][2] *= al1; oc[f][3] *= al1;
        }

        uint32_t pa[4][4];
#pragma unroll
        for (int j = 0; j < 4; ++j) {
            pa[j][0] = packh2(sc[2 * j][0], sc[2 * j][1]);
            pa[j][1] = packh2(sc[2 * j][2], sc[2 * j][3]);
            pa[j][2] = packh2(sc[2 * j + 1][0], sc[2 * j + 1][1]);
            pa[j][3] = packh2(sc[2 * j + 1][2], sc[2 * j + 1][3]);
        }

#pragma unroll
        for (int kb = 0; kb < 4; ++kb) {
            uint32_t bv[4][4];
#pragma unroll
            for (int g = 0; g < 4; ++g)
                ldsm4t(bv[g][0], bv[g][1], bv[g][2], bv[g][3],
                       stg + 8192 +
                           swz((kb * 16 + vRow) * 128 + g * 32 + vColB));
#pragma unroll
            for (int f = 0; f < 8; ++f)
                mma_f16(oc[f], pa[kb], &bv[f >> 1][(f & 1) * 2]);
        }
        __syncthreads();
    }

    const float inv0 = 1.f / l0, inv1 = 1.f / l1;
    const int b = bh >> 4, h = bh & 15;
    const int t0 = qt * 128 + w * 16 + (lane >> 2);
    const size_t mr0 = (size_t)(b * TT + t0) * CC;
    const size_t mr1 = mr0 + (size_t)8 * CC;
#pragma unroll
    for (int f = 0; f < 8; ++f) {
        const int n = h * HD + f * 8 + 2 * (lane & 3);
#pragma unroll
        for (int rr = 0; rr < 2; ++rr) {
            const size_t base = rr ? mr1 : mr0;
            const float va = (rr ? oc[f][2] * inv1 : oc[f][0] * inv0);
            const float vb = (rr ? oc[f][3] * inv1 : oc[f][1] * inv0);
            *(__half2*)&Y16[base + n] = __floats2half2_rn(va, vb);
        }
    }
}

// ---------------------------------------------------------------------------
// launch
// ---------------------------------------------------------------------------
extern "C" void kernel_launch(void* const* d_in, const int* in_sizes, int n_in,
                              void* d_out, int out_size)
{
    (void)in_sizes; (void)n_in; (void)out_size;
    const float* x      = (const float*)d_in[0];
    const float* W_attn = (const float*)d_in[1];
    const float* b_attn = (const float*)d_in[2];
    const float* W_proj = (const float*)d_in[3];
    const float* b_proj = (const float*)d_in[4];
    float* out = (float*)d_out;

    __half *x16, *wa, *wp, *y16, *q16, *k16, *vh;
    cudaGetSymbolAddress((void**)&x16, g_x16);
    cudaGetSymbolAddress((void**)&wa, g_wa);
    cudaGetSymbolAddress((void**)&wp, g_wp);
    cudaGetSymbolAddress((void**)&y16, g_y16);
    cudaGetSymbolAddress((void**)&q16, g_q16);
    cudaGetSymbolAddress((void**)&k16, g_k16);
    cudaGetSymbolAddress((void**)&vh, g_v);

    cudaFuncSetAttribute(gemm_f16_kernel<1>,
                         cudaFuncAttributeMaxDynamicSharedMemorySize,
                         NSTAGE * STAGE);
    cudaFuncSetAttribute(gemm_f16_kernel<0>,
                         cudaFuncAttributeMaxDynamicSharedMemorySize,
                         NSTAGE * STAGE);
    cudaFuncSetAttribute(attn_mma_kernel,
                         cudaFuncAttributeMaxDynamicSharedMemorySize, ATT_SMEM);

    // 0) converts
    {
        const int n4 = MTOT * CC / 4;
        convert_f16_kernel<<<(n4 + 255) / 256, 256>>>(x, x16, n4);
        dim3 tb(32, 8);
        dim3 gb(3 * CC / 32, CC / 32);
        transpose_f16_kernel<<<gb, tb>>>(W_attn, wa, CC, 3 * CC);
        dim3 gp(CC / 32, CC / 32);
        transpose_f16_kernel<<<gp, tb>>>(W_proj, wp, CC, CC);
    }
    // 1) QKV GEMM -> Q/K/V fp16, head-major
    {
        dim3 grid(3 * CC / 128, MTOT / 128);  // (24, 32)
        gemm_f16_kernel<1><<<grid, 256, NSTAGE * STAGE>>>(
            x16, wa, b_attn, nullptr, q16, k16, vh, 3 * CC);
    }
    // 2) attention -> y fp16
    {
        dim3 grid(TT / 128, BB * NH);
        attn_mma_kernel<<<grid, 256, ATT_SMEM>>>(q16, k16, vh, y16);
    }
    // 3) out = y @ W_proj + b_proj
    {
        dim3 grid(CC / 128, MTOT / 128);  // (8, 32)
        gemm_f16_kernel<0><<<grid, 256, NSTAGE * STAGE>>>(
            y16, wp, b_proj, out, nullptr, nullptr, nullptr, CC);
    }
}